// round 3
// baseline (speedup 1.0000x reference)
#include <cuda_runtime.h>
#include <cstdint>

// Problem constants
#define ZB     2
#define NTOK   2048
#define DMODEL 1024
#define HEADS  16
#define DK     64
#define ROWS   (ZB * NTOK)          // 4096
#define SCALE  0.125f               // DK^-0.5

// ---------------------------------------------------------------------------
// Device scratch (no runtime allocation allowed)
// ---------------------------------------------------------------------------
__device__ float g_Q[ZB * HEADS * NTOK * DK];   // [Z,H,N,DK]
__device__ float g_K[ZB * HEADS * NTOK * DK];
__device__ float g_V[ZB * HEADS * NTOK * DK];
__device__ float g_C[ROWS * DMODEL];            // ctx, [Z*N, H*DK]
__device__ float g_Wt[DMODEL * DMODEL];         // out_w transposed -> [in][out]

// ---------------------------------------------------------------------------
// GEMM: Out[z,h,n,k] = sum_d x[z,n,d] * proj[h,d,k] + bias[h,k]
// A: [4096,1024] row-major. B: [H][1024][64]. 64x64x16 tile, 256 thr, 4x4 micro.
// grid = (HEADS, ROWS/64)
// ---------------------------------------------------------------------------
__global__ __launch_bounds__(256) void gemm_qkv(
    const float* __restrict__ A, const float* __restrict__ B,
    const float* __restrict__ bias, float* __restrict__ Out)
{
    const int h  = blockIdx.x;
    const int mb = blockIdx.y;
    __shared__ float As[16][68];
    __shared__ float Bs[16][68];

    const int tid = threadIdx.x;
    const int m0 = (tid >> 4) * 4;
    const int n0 = (tid & 15) * 4;

    float acc[4][4] = {};
    const float* Ab = A + (size_t)mb * 64 * DMODEL;
    const float* Bb = B + (size_t)h * DMODEL * DK;

    for (int k0 = 0; k0 < DMODEL; k0 += 16) {
        {   // load A 64x16 (one float4 / thread), store transposed
            int idx = tid * 4;
            int row = idx >> 4;
            int kc  = idx & 15;
            float4 v = *(const float4*)(Ab + (size_t)row * DMODEL + k0 + kc);
            As[kc + 0][row] = v.x; As[kc + 1][row] = v.y;
            As[kc + 2][row] = v.z; As[kc + 3][row] = v.w;
        }
        {   // load B 16x64 (one float4 / thread), coalesced
            int idx = tid * 4;
            int kk = idx >> 6;
            int n  = idx & 63;
            *(float4*)&Bs[kk][n] = *(const float4*)(Bb + (size_t)(k0 + kk) * DK + n);
        }
        __syncthreads();
        #pragma unroll
        for (int kk = 0; kk < 16; kk++) {
            float4 a = *(float4*)&As[kk][m0];
            float4 b = *(float4*)&Bs[kk][n0];
            acc[0][0] += a.x*b.x; acc[0][1] += a.x*b.y; acc[0][2] += a.x*b.z; acc[0][3] += a.x*b.w;
            acc[1][0] += a.y*b.x; acc[1][1] += a.y*b.y; acc[1][2] += a.y*b.z; acc[1][3] += a.y*b.w;
            acc[2][0] += a.z*b.x; acc[2][1] += a.z*b.y; acc[2][2] += a.z*b.z; acc[2][3] += a.z*b.w;
            acc[3][0] += a.w*b.x; acc[3][1] += a.w*b.y; acc[3][2] += a.w*b.z; acc[3][3] += a.w*b.w;
        }
        __syncthreads();
    }

    #pragma unroll
    for (int i = 0; i < 4; i++) {
        int row = mb * 64 + m0 + i;      // global row in [0,4096)
        int z = row >> 11;
        int n = row & (NTOK - 1);
        #pragma unroll
        for (int j = 0; j < 4; j++) {
            int col = n0 + j;
            Out[(((size_t)z * HEADS + h) * NTOK + n) * DK + col] =
                acc[i][j] + bias[h * DK + col];
        }
    }
}

// ---------------------------------------------------------------------------
// Output-projection GEMM: out[r][c] = sum_d C[r][d] * Wt[d][c]
// grid = (DMODEL/64, ROWS/64)
// ---------------------------------------------------------------------------
__global__ __launch_bounds__(256) void gemm_out(
    const float* __restrict__ A, const float* __restrict__ B,
    float* __restrict__ Out)
{
    const int cb = blockIdx.x;
    const int mb = blockIdx.y;
    __shared__ float As[16][68];
    __shared__ float Bs[16][68];

    const int tid = threadIdx.x;
    const int m0 = (tid >> 4) * 4;
    const int n0 = (tid & 15) * 4;

    float acc[4][4] = {};
    const float* Ab = A + (size_t)mb * 64 * DMODEL;
    const float* Bb = B + (size_t)cb * 64;

    for (int k0 = 0; k0 < DMODEL; k0 += 16) {
        {
            int idx = tid * 4;
            int row = idx >> 4;
            int kc  = idx & 15;
            float4 v = *(const float4*)(Ab + (size_t)row * DMODEL + k0 + kc);
            As[kc + 0][row] = v.x; As[kc + 1][row] = v.y;
            As[kc + 2][row] = v.z; As[kc + 3][row] = v.w;
        }
        {
            int idx = tid * 4;
            int kk = idx >> 6;
            int n  = idx & 63;
            *(float4*)&Bs[kk][n] = *(const float4*)(Bb + (size_t)(k0 + kk) * DMODEL + n);
        }
        __syncthreads();
        #pragma unroll
        for (int kk = 0; kk < 16; kk++) {
            float4 a = *(float4*)&As[kk][m0];
            float4 b = *(float4*)&Bs[kk][n0];
            acc[0][0] += a.x*b.x; acc[0][1] += a.x*b.y; acc[0][2] += a.x*b.z; acc[0][3] += a.x*b.w;
            acc[1][0] += a.y*b.x; acc[1][1] += a.y*b.y; acc[1][2] += a.y*b.z; acc[1][3] += a.y*b.w;
            acc[2][0] += a.z*b.x; acc[2][1] += a.z*b.y; acc[2][2] += a.z*b.z; acc[2][3] += a.z*b.w;
            acc[3][0] += a.w*b.x; acc[3][1] += a.w*b.y; acc[3][2] += a.w*b.z; acc[3][3] += a.w*b.w;
        }
        __syncthreads();
    }

    #pragma unroll
    for (int i = 0; i < 4; i++) {
        int row = mb * 64 + m0 + i;
        #pragma unroll
        for (int j = 0; j < 4; j++)
            Out[(size_t)row * DMODEL + cb * 64 + n0 + j] = acc[i][j];
    }
}

// ---------------------------------------------------------------------------
// 32x32 transpose: Wt[d][c] = W[c][d]
// grid = (32,32), block = (32,8)
// ---------------------------------------------------------------------------
__global__ void transpose1024(const float* __restrict__ W, float* __restrict__ Wt)
{
    __shared__ float tile[32][33];
    int x = blockIdx.x * 32 + threadIdx.x;
    int y = blockIdx.y * 32 + threadIdx.y;
    #pragma unroll
    for (int j = 0; j < 32; j += 8)
        tile[threadIdx.y + j][threadIdx.x] = W[(size_t)(y + j) * DMODEL + x];
    __syncthreads();
    x = blockIdx.y * 32 + threadIdx.x;
    y = blockIdx.x * 32 + threadIdx.y;
    #pragma unroll
    for (int j = 0; j < 32; j += 8)
        Wt[(size_t)(y + j) * DMODEL + x] = tile[threadIdx.x][threadIdx.y + j];
}

// ---------------------------------------------------------------------------
// Attention: one thread owns one query row. 128 queries/block, key tiles of 64.
// Online softmax in 16-key chunks (register-private, no reductions).
// grid = (NTOK/128, Z*HEADS), block = 128
// ---------------------------------------------------------------------------
__global__ __launch_bounds__(128) void attn_kernel(
    const float* __restrict__ Q, const float* __restrict__ K,
    const float* __restrict__ V, const int* __restrict__ mask,
    float* __restrict__ C)
{
    const int qt = blockIdx.x;
    const int zh = blockIdx.y;
    const int z  = zh >> 4;
    const int h  = zh & 15;
    const int tid = threadIdx.x;

    __shared__ float sbuf[2 * 64 * DK];   // K tile | V tile (also Q staging)
    __shared__ int   smk[64];
    float* sK = sbuf;
    float* sV = sbuf + 64 * DK;

    const size_t base = (size_t)zh * NTOK * DK;
    const float* Qb = Q + base;
    const float* Kb = K + base;
    const float* Vb = V + base;

    // ---- stage Q tile (coalesced), then pull this thread's row into regs ----
    {
        const float4* src = (const float4*)(Qb + (size_t)qt * 128 * DK);
        float4* dst = (float4*)sbuf;
        #pragma unroll
        for (int i = tid; i < 128 * DK / 4; i += 128) dst[i] = src[i];
    }
    __syncthreads();
    float4 qv[16];
    {
        const float4* myq = (const float4*)(sbuf + tid * DK);
        #pragma unroll
        for (int i = 0; i < 16; i++) qv[i] = myq[i];
    }
    __syncthreads();

    float4 cv[16];
    #pragma unroll
    for (int i = 0; i < 16; i++) cv[i] = make_float4(0.f, 0.f, 0.f, 0.f);
    float m = -1e30f, l = 0.f;

    for (int kt = 0; kt < NTOK / 64; kt++) {
        // cooperative tile loads (coalesced)
        {
            const float4* ks = (const float4*)(Kb + (size_t)kt * 64 * DK);
            const float4* vs = (const float4*)(Vb + (size_t)kt * 64 * DK);
            float4* kd = (float4*)sK;
            float4* vd = (float4*)sV;
            #pragma unroll
            for (int i = tid; i < 64 * DK / 4; i += 128) { kd[i] = ks[i]; vd[i] = vs[i]; }
            if (tid < 64) smk[tid] = mask[z * NTOK + kt * 64 + tid];
        }
        __syncthreads();

        #pragma unroll
        for (int c = 0; c < 4; c++) {
            float s[16];
            int msk[16];
            #pragma unroll
            for (int j = 0; j < 16; j++) {
                int kk = c * 16 + j;
                const float4* Kr = (const float4*)(sK + kk * DK);
                float s0 = 0.f, s1 = 0.f, s2 = 0.f, s3 = 0.f;
                #pragma unroll
                for (int i = 0; i < 16; i += 4) {
                    float4 k0 = Kr[i], k1 = Kr[i+1], k2 = Kr[i+2], k3 = Kr[i+3];
                    s0 += qv[i  ].x*k0.x + qv[i  ].y*k0.y + qv[i  ].z*k0.z + qv[i  ].w*k0.w;
                    s1 += qv[i+1].x*k1.x + qv[i+1].y*k1.y + qv[i+1].z*k1.z + qv[i+1].w*k1.w;
                    s2 += qv[i+2].x*k2.x + qv[i+2].y*k2.y + qv[i+2].z*k2.z + qv[i+2].w*k2.w;
                    s3 += qv[i+3].x*k3.x + qv[i+3].y*k3.y + qv[i+3].z*k3.z + qv[i+3].w*k3.w;
                }
                msk[j] = smk[kk];
                s[j] = msk[j] ? ((s0 + s1) + (s2 + s3)) * SCALE : -1e30f;
            }
            float cm = s[0];
            #pragma unroll
            for (int j = 1; j < 16; j++) cm = fmaxf(cm, s[j]);
            float mn = fmaxf(m, cm);
            float corr = __expf(m - mn);
            l *= corr;
            #pragma unroll
            for (int i = 0; i < 16; i++) {
                cv[i].x *= corr; cv[i].y *= corr; cv[i].z *= corr; cv[i].w *= corr;
            }
            #pragma unroll
            for (int j = 0; j < 16; j++) {
                float p = msk[j] ? __expf(s[j] - mn) : 0.f;
                l += p;
                const float4* Vr = (const float4*)(sV + (c * 16 + j) * DK);
                #pragma unroll
                for (int i = 0; i < 16; i++) {
                    float4 v = Vr[i];
                    cv[i].x += p * v.x; cv[i].y += p * v.y;
                    cv[i].z += p * v.z; cv[i].w += p * v.w;
                }
            }
            m = mn;
        }
        __syncthreads();
    }

    // epilogue: normalize, zero invalid queries, write ctx[z*N+tok][h*64..]
    const int tok = qt * 128 + tid;
    const int qvalid = mask[z * NTOK + tok];
    const float inv = (qvalid && l > 0.f) ? 1.0f / l : 0.f;
    float4* outp = (float4*)(C + ((size_t)(z * NTOK + tok) * DMODEL + h * DK));
    #pragma unroll
    for (int i = 0; i < 16; i++) {
        float4 o;
        o.x = cv[i].x * inv; o.y = cv[i].y * inv;
        o.z = cv[i].z * inv; o.w = cv[i].w * inv;
        outp[i] = o;
    }
}

// ---------------------------------------------------------------------------
// Host entry
// ---------------------------------------------------------------------------
extern "C" void kernel_launch(void* const* d_in, const int* in_sizes, int n_in,
                              void* d_out, int out_size)
{
    const float* x     = (const float*)d_in[0];
    const int*   mask  = (const int*)  d_in[1];
    const float* qproj = (const float*)d_in[2];
    const float* kproj = (const float*)d_in[3];
    const float* vproj = (const float*)d_in[4];
    const float* qbias = (const float*)d_in[5];
    const float* kbias = (const float*)d_in[6];
    const float* vbias = (const float*)d_in[7];
    const float* outw  = (const float*)d_in[8];
    float* out = (float*)d_out;

    float *Q, *K, *V, *C, *Wt;
    cudaGetSymbolAddress((void**)&Q,  g_Q);
    cudaGetSymbolAddress((void**)&K,  g_K);
    cudaGetSymbolAddress((void**)&V,  g_V);
    cudaGetSymbolAddress((void**)&C,  g_C);
    cudaGetSymbolAddress((void**)&Wt, g_Wt);

    dim3 gg(HEADS, ROWS / 64);
    gemm_qkv<<<gg, 256>>>(x, qproj, qbias, Q);
    gemm_qkv<<<gg, 256>>>(x, kproj, kbias, K);
    gemm_qkv<<<gg, 256>>>(x, vproj, vbias, V);

    attn_kernel<<<dim3(NTOK / 128, ZB * HEADS), 128>>>(Q, K, V, mask, C);

    transpose1024<<<dim3(32, 32), dim3(32, 8)>>>(outw, Wt);
    gemm_out<<<dim3(DMODEL / 64, ROWS / 64), 256>>>(C, Wt, out);
}

// round 4
// speedup vs baseline: 2.4575x; 2.4575x over previous
#include <cuda_runtime.h>
#include <cuda_bf16.h>
#include <cstdint>

// Problem constants
#define ZB     2
#define NTOK   2048
#define DMODEL 1024
#define HEADS  16
#define DK     64
#define ROWS   (ZB * NTOK)          // 4096
#define SCALE  0.125f               // DK^-0.5
#define ZH     (ZB * HEADS)         // 32

// ---------------------------------------------------------------------------
// Device scratch (no runtime allocation allowed)
// ---------------------------------------------------------------------------
__device__ float g_Q[ZH * NTOK * DK];           // [zh, n, dk] fp32
__device__ float g_K[ZH * NTOK * DK];
__device__ float g_V[ZH * NTOK * DK];
__device__ float g_C[ROWS * DMODEL];            // ctx, [Z*N, H*DK]
__device__ float g_Wt[DMODEL * DMODEL];         // out_w transposed -> [in][out]

// bf16 hi/lo split copies for tensor-core attention
__device__ __nv_bfloat16 g_Kh[ZH * NTOK * DK];  // [zh][key][dk]
__device__ __nv_bfloat16 g_Kl[ZH * NTOK * DK];
__device__ __nv_bfloat16 g_Vth[ZH * DK * NTOK]; // transposed: [zh][dk][key]
__device__ __nv_bfloat16 g_Vtl[ZH * DK * NTOK];

// ---------------------------------------------------------------------------
// helpers
// ---------------------------------------------------------------------------
__device__ __forceinline__ uint32_t packb(__nv_bfloat16 x, __nv_bfloat16 y) {
    return (uint32_t)__bfloat16_as_ushort(x) |
           ((uint32_t)__bfloat16_as_ushort(y) << 16);
}
__device__ __forceinline__ void split1(float x, __nv_bfloat16& h, __nv_bfloat16& l) {
    h = __float2bfloat16(x);
    l = __float2bfloat16(x - __bfloat162float(h));
}
// split a pair of floats into packed (hi,hi) and (lo,lo) b32 regs (elem0 = low half)
__device__ __forceinline__ void split2(float x, float y, uint32_t& hi, uint32_t& lo) {
    __nv_bfloat16 xh, xl, yh, yl;
    split1(x, xh, xl);
    split1(y, yh, yl);
    hi = packb(xh, yh);
    lo = packb(xl, yl);
}

__device__ __forceinline__ void mma_bf16(
    float& c0, float& c1, float& c2, float& c3,
    uint32_t a0, uint32_t a1, uint32_t a2, uint32_t a3,
    uint32_t b0, uint32_t b1)
{
    asm volatile(
        "mma.sync.aligned.m16n8k16.row.col.f32.bf16.bf16.f32 "
        "{%0,%1,%2,%3},{%4,%5,%6,%7},{%8,%9},{%0,%1,%2,%3};\n"
        : "+f"(c0), "+f"(c1), "+f"(c2), "+f"(c3)
        : "r"(a0), "r"(a1), "r"(a2), "r"(a3), "r"(b0), "r"(b1));
}

// ---------------------------------------------------------------------------
// GEMM: Out[z,h,n,k] = sum_d x[z,n,d] * proj[h,d,k] + bias[h,k]   (fp32)
// grid = (HEADS, ROWS/64)
// ---------------------------------------------------------------------------
__global__ __launch_bounds__(256) void gemm_qkv(
    const float* __restrict__ A, const float* __restrict__ B,
    const float* __restrict__ bias, float* __restrict__ Out)
{
    const int h  = blockIdx.x;
    const int mb = blockIdx.y;
    __shared__ float As[16][68];
    __shared__ float Bs[16][68];

    const int tid = threadIdx.x;
    const int m0 = (tid >> 4) * 4;
    const int n0 = (tid & 15) * 4;

    float acc[4][4] = {};
    const float* Ab = A + (size_t)mb * 64 * DMODEL;
    const float* Bb = B + (size_t)h * DMODEL * DK;

    for (int k0 = 0; k0 < DMODEL; k0 += 16) {
        {
            int idx = tid * 4;
            int row = idx >> 4;
            int kc  = idx & 15;
            float4 v = *(const float4*)(Ab + (size_t)row * DMODEL + k0 + kc);
            As[kc + 0][row] = v.x; As[kc + 1][row] = v.y;
            As[kc + 2][row] = v.z; As[kc + 3][row] = v.w;
        }
        {
            int idx = tid * 4;
            int kk = idx >> 6;
            int n  = idx & 63;
            *(float4*)&Bs[kk][n] = *(const float4*)(Bb + (size_t)(k0 + kk) * DK + n);
        }
        __syncthreads();
        #pragma unroll
        for (int kk = 0; kk < 16; kk++) {
            float4 a = *(float4*)&As[kk][m0];
            float4 b = *(float4*)&Bs[kk][n0];
            acc[0][0] += a.x*b.x; acc[0][1] += a.x*b.y; acc[0][2] += a.x*b.z; acc[0][3] += a.x*b.w;
            acc[1][0] += a.y*b.x; acc[1][1] += a.y*b.y; acc[1][2] += a.y*b.z; acc[1][3] += a.y*b.w;
            acc[2][0] += a.z*b.x; acc[2][1] += a.z*b.y; acc[2][2] += a.z*b.z; acc[2][3] += a.z*b.w;
            acc[3][0] += a.w*b.x; acc[3][1] += a.w*b.y; acc[3][2] += a.w*b.z; acc[3][3] += a.w*b.w;
        }
        __syncthreads();
    }

    #pragma unroll
    for (int i = 0; i < 4; i++) {
        int row = mb * 64 + m0 + i;
        int z = row >> 11;
        int n = row & (NTOK - 1);
        #pragma unroll
        for (int j = 0; j < 4; j++) {
            int col = n0 + j;
            Out[(((size_t)z * HEADS + h) * NTOK + n) * DK + col] =
                acc[i][j] + bias[h * DK + col];
        }
    }
}

// ---------------------------------------------------------------------------
// Output-projection GEMM (fp32): out[r][c] = sum_d C[r][d] * Wt[d][c]
// ---------------------------------------------------------------------------
__global__ __launch_bounds__(256) void gemm_out(
    const float* __restrict__ A, const float* __restrict__ B,
    float* __restrict__ Out)
{
    const int cb = blockIdx.x;
    const int mb = blockIdx.y;
    __shared__ float As[16][68];
    __shared__ float Bs[16][68];

    const int tid = threadIdx.x;
    const int m0 = (tid >> 4) * 4;
    const int n0 = (tid & 15) * 4;

    float acc[4][4] = {};
    const float* Ab = A + (size_t)mb * 64 * DMODEL;
    const float* Bb = B + (size_t)cb * 64;

    for (int k0 = 0; k0 < DMODEL; k0 += 16) {
        {
            int idx = tid * 4;
            int row = idx >> 4;
            int kc  = idx & 15;
            float4 v = *(const float4*)(Ab + (size_t)row * DMODEL + k0 + kc);
            As[kc + 0][row] = v.x; As[kc + 1][row] = v.y;
            As[kc + 2][row] = v.z; As[kc + 3][row] = v.w;
        }
        {
            int idx = tid * 4;
            int kk = idx >> 6;
            int n  = idx & 63;
            *(float4*)&Bs[kk][n] = *(const float4*)(Bb + (size_t)(k0 + kk) * DMODEL + n);
        }
        __syncthreads();
        #pragma unroll
        for (int kk = 0; kk < 16; kk++) {
            float4 a = *(float4*)&As[kk][m0];
            float4 b = *(float4*)&Bs[kk][n0];
            acc[0][0] += a.x*b.x; acc[0][1] += a.x*b.y; acc[0][2] += a.x*b.z; acc[0][3] += a.x*b.w;
            acc[1][0] += a.y*b.x; acc[1][1] += a.y*b.y; acc[1][2] += a.y*b.z; acc[1][3] += a.y*b.w;
            acc[2][0] += a.z*b.x; acc[2][1] += a.z*b.y; acc[2][2] += a.z*b.z; acc[2][3] += a.z*b.w;
            acc[3][0] += a.w*b.x; acc[3][1] += a.w*b.y; acc[3][2] += a.w*b.z; acc[3][3] += a.w*b.w;
        }
        __syncthreads();
    }

    #pragma unroll
    for (int i = 0; i < 4; i++) {
        int row = mb * 64 + m0 + i;
        #pragma unroll
        for (int j = 0; j < 4; j++)
            Out[(size_t)row * DMODEL + cb * 64 + n0 + j] = acc[i][j];
    }
}

// ---------------------------------------------------------------------------
// 32x32 transpose: Wt[d][c] = W[c][d]
// ---------------------------------------------------------------------------
__global__ void transpose1024(const float* __restrict__ W, float* __restrict__ Wt)
{
    __shared__ float tile[32][33];
    int x = blockIdx.x * 32 + threadIdx.x;
    int y = blockIdx.y * 32 + threadIdx.y;
    #pragma unroll
    for (int j = 0; j < 32; j += 8)
        tile[threadIdx.y + j][threadIdx.x] = W[(size_t)(y + j) * DMODEL + x];
    __syncthreads();
    x = blockIdx.y * 32 + threadIdx.x;
    y = blockIdx.x * 32 + threadIdx.y;
    #pragma unroll
    for (int j = 0; j < 32; j += 8)
        Wt[(size_t)(y + j) * DMODEL + x] = tile[threadIdx.x][threadIdx.y + j];
}

// ---------------------------------------------------------------------------
// K split: elementwise fp32 -> (hi, lo) bf16, same [zh][key][dk] layout
// ---------------------------------------------------------------------------
__global__ void split_k_kernel(const float* __restrict__ in,
                               __nv_bfloat16* __restrict__ hi,
                               __nv_bfloat16* __restrict__ lo)
{
    const int n = ZH * NTOK * DK;
    for (int i = blockIdx.x * blockDim.x + threadIdx.x; i < n;
         i += gridDim.x * blockDim.x) {
        float x = in[i];
        __nv_bfloat16 h, l;
        split1(x, h, l);
        hi[i] = h;
        lo[i] = l;
    }
}

// ---------------------------------------------------------------------------
// V split + transpose: Vt[zh][dk][key] = split(V[zh][key][dk])
// grid = (NTOK/64, ZH), block = 128
// ---------------------------------------------------------------------------
__global__ __launch_bounds__(128) void split_vt_kernel(
    const float* __restrict__ V,
    __nv_bfloat16* __restrict__ Vth, __nv_bfloat16* __restrict__ Vtl)
{
    const int kt = blockIdx.x;
    const int zh = blockIdx.y;
    const int tid = threadIdx.x;
    __shared__ float tile[64][65];

    const float* src = V + (size_t)zh * NTOK * DK + (size_t)kt * 64 * DK;
    #pragma unroll
    for (int it = 0; it < 8; it++) {
        int i4 = tid + it * 128;          // float4 index over 64x16
        int key = i4 >> 4;
        int d4 = (i4 & 15) * 4;
        float4 v = *(const float4*)(src + (size_t)key * DK + d4);
        tile[key][d4 + 0] = v.x; tile[key][d4 + 1] = v.y;
        tile[key][d4 + 2] = v.z; tile[key][d4 + 3] = v.w;
    }
    __syncthreads();
    #pragma unroll
    for (int it = 0; it < 32; it++) {
        int o = tid + it * 128;           // over 4096 outputs
        int dk = o >> 6;
        int key = o & 63;
        float x = tile[key][dk];
        __nv_bfloat16 h, l;
        split1(x, h, l);
        size_t idx = (size_t)zh * DK * NTOK + (size_t)dk * NTOK + kt * 64 + key;
        Vth[idx] = h;
        Vtl[idx] = l;
    }
}

// ---------------------------------------------------------------------------
// Flash attention with m16n8k16 bf16 MMA, 3-term hi/lo split (~fp32 accuracy).
// Block = 128 threads (4 warps), 64 queries/block (16 per warp).
// grid = (NTOK/64, ZH)
// ---------------------------------------------------------------------------
__global__ __launch_bounds__(128) void attn_mma(
    const float* __restrict__ Q,
    const __nv_bfloat16* __restrict__ Kh, const __nv_bfloat16* __restrict__ Kl,
    const __nv_bfloat16* __restrict__ Vth, const __nv_bfloat16* __restrict__ Vtl,
    const int* __restrict__ mask, float* __restrict__ C)
{
    const int qt   = blockIdx.x;          // query tile (64 queries)
    const int zh   = blockIdx.y;
    const int z    = zh >> 4;
    const int h    = zh & 15;
    const int tid  = threadIdx.x;
    const int warp = tid >> 5;
    const int lane = tid & 31;
    const int g    = lane >> 2;           // groupID
    const int tg   = lane & 3;            // thread-in-group

    // SMEM: 4 padded bf16 tiles [64][72] (144B rows, 16B-aligned) + mask
    __shared__ __align__(16) unsigned char smem_raw[4 * 64 * 72 * 2 + 256];
    typedef __nv_bfloat16(*tile_t)[72];
    tile_t sKh = (tile_t)(smem_raw);
    tile_t sKl = (tile_t)(smem_raw + 9216);
    tile_t sVh = (tile_t)(smem_raw + 18432);
    tile_t sVl = (tile_t)(smem_raw + 27648);
    int* smk   = (int*)(smem_raw + 36864);

    const size_t base  = (size_t)zh * NTOK * DK;    // K layout
    const size_t baseT = (size_t)zh * DK * NTOK;    // Vt layout

    // ---- stage Q tile (fp32) into smem, build per-warp A fragments ----
    {
        float4* dst = (float4*)smem_raw;
        const float4* src = (const float4*)(Q + base + (size_t)qt * 64 * DK);
        #pragma unroll
        for (int i = tid; i < 64 * DK / 4; i += 128) dst[i] = src[i];
    }
    __syncthreads();

    uint32_t Qh[4][4], Ql[4][4];
    {
        const float* sQ = (const float*)smem_raw;
        int r0 = warp * 16 + g;
        int r1 = r0 + 8;
        #pragma unroll
        for (int kk = 0; kk < 4; kk++) {
            int c = kk * 16 + 2 * tg;
            // fold softmax scale into Q
            split2(SCALE * sQ[r0 * 64 + c],     SCALE * sQ[r0 * 64 + c + 1], Qh[kk][0], Ql[kk][0]);
            split2(SCALE * sQ[r1 * 64 + c],     SCALE * sQ[r1 * 64 + c + 1], Qh[kk][1], Ql[kk][1]);
            split2(SCALE * sQ[r0 * 64 + c + 8], SCALE * sQ[r0 * 64 + c + 9], Qh[kk][2], Ql[kk][2]);
            split2(SCALE * sQ[r1 * 64 + c + 8], SCALE * sQ[r1 * 64 + c + 9], Qh[kk][3], Ql[kk][3]);
        }
    }
    __syncthreads();

    float O[8][4];
    #pragma unroll
    for (int nt = 0; nt < 8; nt++)
        O[nt][0] = O[nt][1] = O[nt][2] = O[nt][3] = 0.f;
    float m0 = -1e30f, m1 = -1e30f, l0 = 0.f, l1 = 0.f;

    for (int kt = 0; kt < NTOK / 64; kt++) {
        // ---- cooperative tile load (pure uint4 copies, pre-split bf16) ----
        {
            const __nv_bfloat16* gkh = Kh + base + (size_t)kt * 64 * DK;
            const __nv_bfloat16* gkl = Kl + base + (size_t)kt * 64 * DK;
            #pragma unroll
            for (int it = 0; it < 4; it++) {
                int i = tid + it * 128;      // uint4 index over 64x(64/8)
                int row = i >> 3;
                int c8 = (i & 7) * 8;
                *(uint4*)&sKh[row][c8] = *(const uint4*)(gkh + (size_t)row * DK + c8);
                *(uint4*)&sKl[row][c8] = *(const uint4*)(gkl + (size_t)row * DK + c8);
                // V transposed tiles: row = dk, cols = keys
                *(uint4*)&sVh[row][c8] =
                    *(const uint4*)(Vth + baseT + (size_t)row * NTOK + kt * 64 + c8);
                *(uint4*)&sVl[row][c8] =
                    *(const uint4*)(Vtl + baseT + (size_t)row * NTOK + kt * 64 + c8);
            }
            if (tid < 64) smk[tid] = mask[z * NTOK + kt * 64 + tid];
        }
        __syncthreads();

        // ---- S = (Q*scale) x K^T  (bf16x3) ----
        float S[8][4];
        #pragma unroll
        for (int nt = 0; nt < 8; nt++) {
            S[nt][0] = S[nt][1] = S[nt][2] = S[nt][3] = 0.f;
            #pragma unroll
            for (int kk = 0; kk < 4; kk++) {
                uint32_t bh0 = *(const uint32_t*)&sKh[nt * 8 + g][kk * 16 + 2 * tg];
                uint32_t bh1 = *(const uint32_t*)&sKh[nt * 8 + g][kk * 16 + 8 + 2 * tg];
                uint32_t bl0 = *(const uint32_t*)&sKl[nt * 8 + g][kk * 16 + 2 * tg];
                uint32_t bl1 = *(const uint32_t*)&sKl[nt * 8 + g][kk * 16 + 8 + 2 * tg];
                mma_bf16(S[nt][0], S[nt][1], S[nt][2], S[nt][3],
                         Qh[kk][0], Qh[kk][1], Qh[kk][2], Qh[kk][3], bh0, bh1);
                mma_bf16(S[nt][0], S[nt][1], S[nt][2], S[nt][3],
                         Qh[kk][0], Qh[kk][1], Qh[kk][2], Qh[kk][3], bl0, bl1);
                mma_bf16(S[nt][0], S[nt][1], S[nt][2], S[nt][3],
                         Ql[kk][0], Ql[kk][1], Ql[kk][2], Ql[kk][3], bh0, bh1);
            }
        }

        // ---- mask + online softmax (rows g and g+8) ----
        float mx0 = -1e30f, mx1 = -1e30f;
        #pragma unroll
        for (int nt = 0; nt < 8; nt++) {
            #pragma unroll
            for (int j = 0; j < 2; j++) {
                int key = nt * 8 + 2 * tg + j;
                bool ok = smk[key] != 0;
                float v0 = ok ? S[nt][j]     : -1e9f;
                float v1 = ok ? S[nt][2 + j] : -1e9f;
                S[nt][j] = v0; S[nt][2 + j] = v1;
                mx0 = fmaxf(mx0, v0); mx1 = fmaxf(mx1, v1);
            }
        }
        mx0 = fmaxf(mx0, __shfl_xor_sync(0xffffffffu, mx0, 1));
        mx0 = fmaxf(mx0, __shfl_xor_sync(0xffffffffu, mx0, 2));
        mx1 = fmaxf(mx1, __shfl_xor_sync(0xffffffffu, mx1, 1));
        mx1 = fmaxf(mx1, __shfl_xor_sync(0xffffffffu, mx1, 2));

        float mn0 = fmaxf(m0, mx0), mn1 = fmaxf(m1, mx1);
        float corr0 = __expf(m0 - mn0), corr1 = __expf(m1 - mn1);
        m0 = mn0; m1 = mn1;

        float ls0 = 0.f, ls1 = 0.f;
        #pragma unroll
        for (int nt = 0; nt < 8; nt++) {
            S[nt][0] = __expf(S[nt][0] - m0); ls0 += S[nt][0];
            S[nt][1] = __expf(S[nt][1] - m0); ls0 += S[nt][1];
            S[nt][2] = __expf(S[nt][2] - m1); ls1 += S[nt][2];
            S[nt][3] = __expf(S[nt][3] - m1); ls1 += S[nt][3];
        }
        ls0 += __shfl_xor_sync(0xffffffffu, ls0, 1);
        ls0 += __shfl_xor_sync(0xffffffffu, ls0, 2);
        ls1 += __shfl_xor_sync(0xffffffffu, ls1, 1);
        ls1 += __shfl_xor_sync(0xffffffffu, ls1, 2);
        l0 = l0 * corr0 + ls0;
        l1 = l1 * corr1 + ls1;

        #pragma unroll
        for (int nt = 0; nt < 8; nt++) {
            O[nt][0] *= corr0; O[nt][1] *= corr0;
            O[nt][2] *= corr1; O[nt][3] *= corr1;
        }

        // ---- O += P x V  (bf16x3; P fragments come straight from S) ----
        #pragma unroll
        for (int kk = 0; kk < 4; kk++) {
            uint32_t ah[4], al[4];
            split2(S[2 * kk][0],     S[2 * kk][1],     ah[0], al[0]);
            split2(S[2 * kk][2],     S[2 * kk][3],     ah[1], al[1]);
            split2(S[2 * kk + 1][0], S[2 * kk + 1][1], ah[2], al[2]);
            split2(S[2 * kk + 1][2], S[2 * kk + 1][3], ah[3], al[3]);
            #pragma unroll
            for (int nt = 0; nt < 8; nt++) {
                uint32_t bh0 = *(const uint32_t*)&sVh[nt * 8 + g][kk * 16 + 2 * tg];
                uint32_t bh1 = *(const uint32_t*)&sVh[nt * 8 + g][kk * 16 + 8 + 2 * tg];
                uint32_t bl0 = *(const uint32_t*)&sVl[nt * 8 + g][kk * 16 + 2 * tg];
                uint32_t bl1 = *(const uint32_t*)&sVl[nt * 8 + g][kk * 16 + 8 + 2 * tg];
                mma_bf16(O[nt][0], O[nt][1], O[nt][2], O[nt][3],
                         ah[0], ah[1], ah[2], ah[3], bh0, bh1);
                mma_bf16(O[nt][0], O[nt][1], O[nt][2], O[nt][3],
                         ah[0], ah[1], ah[2], ah[3], bl0, bl1);
                mma_bf16(O[nt][0], O[nt][1], O[nt][2], O[nt][3],
                         al[0], al[1], al[2], al[3], bh0, bh1);
            }
        }
        __syncthreads();
    }

    // ---- epilogue: normalize, zero invalid queries, write ctx ----
    const int tok0 = qt * 64 + warp * 16 + g;
    const int tok1 = tok0 + 8;
    const int qv0 = mask[z * NTOK + tok0];
    const int qv1 = mask[z * NTOK + tok1];
    const float inv0 = (qv0 && l0 > 0.f) ? 1.0f / l0 : 0.f;
    const float inv1 = (qv1 && l1 > 0.f) ? 1.0f / l1 : 0.f;

    #pragma unroll
    for (int nt = 0; nt < 8; nt++) {
        int dk = nt * 8 + 2 * tg;
        float2 o0 = make_float2(O[nt][0] * inv0, O[nt][1] * inv0);
        float2 o1 = make_float2(O[nt][2] * inv1, O[nt][3] * inv1);
        *(float2*)&C[((size_t)(z * NTOK + tok0)) * DMODEL + h * DK + dk] = o0;
        *(float2*)&C[((size_t)(z * NTOK + tok1)) * DMODEL + h * DK + dk] = o1;
    }
}

// ---------------------------------------------------------------------------
// Host entry
// ---------------------------------------------------------------------------
extern "C" void kernel_launch(void* const* d_in, const int* in_sizes, int n_in,
                              void* d_out, int out_size)
{
    const float* x     = (const float*)d_in[0];
    const int*   mask  = (const int*)  d_in[1];
    const float* qproj = (const float*)d_in[2];
    const float* kproj = (const float*)d_in[3];
    const float* vproj = (const float*)d_in[4];
    const float* qbias = (const float*)d_in[5];
    const float* kbias = (const float*)d_in[6];
    const float* vbias = (const float*)d_in[7];
    const float* outw  = (const float*)d_in[8];
    float* out = (float*)d_out;

    float *Q, *K, *V, *C, *Wt;
    __nv_bfloat16 *Kh, *Kl, *Vth, *Vtl;
    cudaGetSymbolAddress((void**)&Q,   g_Q);
    cudaGetSymbolAddress((void**)&K,   g_K);
    cudaGetSymbolAddress((void**)&V,   g_V);
    cudaGetSymbolAddress((void**)&C,   g_C);
    cudaGetSymbolAddress((void**)&Wt,  g_Wt);
    cudaGetSymbolAddress((void**)&Kh,  g_Kh);
    cudaGetSymbolAddress((void**)&Kl,  g_Kl);
    cudaGetSymbolAddress((void**)&Vth, g_Vth);
    cudaGetSymbolAddress((void**)&Vtl, g_Vtl);

    dim3 gg(HEADS, ROWS / 64);
    gemm_qkv<<<gg, 256>>>(x, qproj, qbias, Q);
    gemm_qkv<<<gg, 256>>>(x, kproj, kbias, K);
    gemm_qkv<<<gg, 256>>>(x, vproj, vbias, V);

    split_k_kernel<<<2048, 256>>>(K, Kh, Kl);
    split_vt_kernel<<<dim3(NTOK / 64, ZH), 128>>>(V, Vth, Vtl);

    attn_mma<<<dim3(NTOK / 64, ZH), 128>>>(Q, Kh, Kl, Vth, Vtl, mask, C);

    transpose1024<<<dim3(32, 32), dim3(32, 8)>>>(outw, Wt);
    gemm_out<<<dim3(DMODEL / 64, ROWS / 64), 256>>>(C, Wt, out);
}

// round 5
// speedup vs baseline: 3.6742x; 1.4951x over previous
#include <cuda_runtime.h>
#include <cuda_bf16.h>
#include <cstdint>

// Problem constants
#define ZB     2
#define NTOK   2048
#define DMODEL 1024
#define HEADS  16
#define DK     64
#define ROWS   (ZB * NTOK)          // 4096
#define SCALE  0.125f               // DK^-0.5
#define ZH     (ZB * HEADS)         // 32

// ---------------------------------------------------------------------------
// Device scratch (no runtime allocation allowed)
// ---------------------------------------------------------------------------
__device__ float g_Q[ZH * NTOK * DK];           // [zh, n, dk] fp32
__device__ float g_K[ZH * NTOK * DK];
__device__ float g_V[ZH * NTOK * DK];

// split inputs for MMA GEMMs
__device__ __nv_bfloat16 g_Xh[ROWS * DMODEL];   // x split
__device__ __nv_bfloat16 g_Xl[ROWS * DMODEL];
__device__ __nv_bfloat16 g_BQh[HEADS * DK * DMODEL];  // proj split, [h][n][k]
__device__ __nv_bfloat16 g_BQl[HEADS * DK * DMODEL];
__device__ __nv_bfloat16 g_BKh[HEADS * DK * DMODEL];
__device__ __nv_bfloat16 g_BKl[HEADS * DK * DMODEL];
__device__ __nv_bfloat16 g_BVh[HEADS * DK * DMODEL];
__device__ __nv_bfloat16 g_BVl[HEADS * DK * DMODEL];
__device__ __nv_bfloat16 g_Wh[DMODEL * DMODEL]; // out_w split ([n][k] = native)
__device__ __nv_bfloat16 g_Wl[DMODEL * DMODEL];
__device__ __nv_bfloat16 g_Ch[ROWS * DMODEL];   // ctx split (attention output)
__device__ __nv_bfloat16 g_Cl[ROWS * DMODEL];

// bf16 hi/lo split copies for tensor-core attention
__device__ __nv_bfloat16 g_Kh[ZH * NTOK * DK];  // [zh][key][dk]
__device__ __nv_bfloat16 g_Kl[ZH * NTOK * DK];
__device__ __nv_bfloat16 g_Vth[ZH * DK * NTOK]; // transposed: [zh][dk][key]
__device__ __nv_bfloat16 g_Vtl[ZH * DK * NTOK];

// ---------------------------------------------------------------------------
// helpers
// ---------------------------------------------------------------------------
__device__ __forceinline__ uint32_t packb(__nv_bfloat16 x, __nv_bfloat16 y) {
    return (uint32_t)__bfloat16_as_ushort(x) |
           ((uint32_t)__bfloat16_as_ushort(y) << 16);
}
__device__ __forceinline__ void split1(float x, __nv_bfloat16& h, __nv_bfloat16& l) {
    h = __float2bfloat16(x);
    l = __float2bfloat16(x - __bfloat162float(h));
}
__device__ __forceinline__ void split2(float x, float y, uint32_t& hi, uint32_t& lo) {
    __nv_bfloat16 xh, xl, yh, yl;
    split1(x, xh, xl);
    split1(y, yh, yl);
    hi = packb(xh, yh);
    lo = packb(xl, yl);
}

__device__ __forceinline__ void mma_bf16(
    float& c0, float& c1, float& c2, float& c3,
    uint32_t a0, uint32_t a1, uint32_t a2, uint32_t a3,
    uint32_t b0, uint32_t b1)
{
    asm volatile(
        "mma.sync.aligned.m16n8k16.row.col.f32.bf16.bf16.f32 "
        "{%0,%1,%2,%3},{%4,%5,%6,%7},{%8,%9},{%0,%1,%2,%3};\n"
        : "+f"(c0), "+f"(c1), "+f"(c2), "+f"(c3)
        : "r"(a0), "r"(a1), "r"(a2), "r"(a3), "r"(b0), "r"(b1));
}

// ---------------------------------------------------------------------------
// Elementwise split: fp32 -> (hi, lo) bf16
// ---------------------------------------------------------------------------
__global__ void split_any_kernel(const float* __restrict__ in,
                                 __nv_bfloat16* __restrict__ hi,
                                 __nv_bfloat16* __restrict__ lo, int n)
{
    for (int i = blockIdx.x * blockDim.x + threadIdx.x; i < n;
         i += gridDim.x * blockDim.x) {
        float x = in[i];
        __nv_bfloat16 h, l;
        split1(x, h, l);
        hi[i] = h;
        lo[i] = l;
    }
}

// ---------------------------------------------------------------------------
// Proj split + transpose: proj[h][d][n] (fp32) -> B[h][n][d] hi/lo (bf16)
// grid = (DMODEL/64, HEADS), block = 256
// ---------------------------------------------------------------------------
__global__ __launch_bounds__(256) void split_proj_kernel(
    const float* __restrict__ proj,
    __nv_bfloat16* __restrict__ Bh, __nv_bfloat16* __restrict__ Bl)
{
    const int dt = blockIdx.x;      // 64-wide d tile
    const int h  = blockIdx.y;
    const int tid = threadIdx.x;
    __shared__ float tile[64][65];

    const float* src = proj + ((size_t)h * DMODEL + dt * 64) * DK;
    #pragma unroll
    for (int it = 0; it < 4; it++) {
        int i4 = tid + it * 256;        // float4 index over 64x16
        int r  = i4 >> 4;               // d-local
        int c4 = (i4 & 15) * 4;         // n
        float4 v = *(const float4*)(src + (size_t)r * DK + c4);
        tile[r][c4 + 0] = v.x; tile[r][c4 + 1] = v.y;
        tile[r][c4 + 2] = v.z; tile[r][c4 + 3] = v.w;
    }
    __syncthreads();
    #pragma unroll
    for (int it = 0; it < 16; it++) {
        int o = tid + it * 256;         // over 4096 outputs
        int n = o >> 6;
        int j = o & 63;                 // d-local
        float x = tile[j][n];
        __nv_bfloat16 hh, ll;
        split1(x, hh, ll);
        size_t idx = ((size_t)h * DK + n) * DMODEL + dt * 64 + j;
        Bh[idx] = hh;
        Bl[idx] = ll;
    }
}

// ---------------------------------------------------------------------------
// bf16x3 MMA GEMM, 128x64 block tile, K=1024 in chunks of 32.
// C[m][n] = sum_k A[m][k]*B[n][k]  (A row-major [m][k], B n-major [n][k])
// 256 threads = 8 warps, each warp 16 rows x 64 cols.
// ---------------------------------------------------------------------------
__device__ __forceinline__ void gemm_bf3_core(
    const __nv_bfloat16* __restrict__ Ahb, const __nv_bfloat16* __restrict__ Alb,
    const __nv_bfloat16* __restrict__ Bhb, const __nv_bfloat16* __restrict__ Blb,
    float O[8][4])
{
    __shared__ __nv_bfloat16 sAh[128][40], sAl[128][40];
    __shared__ __nv_bfloat16 sBh[64][40],  sBl[64][40];

    const int tid  = threadIdx.x;
    const int warp = tid >> 5;
    const int lane = tid & 31;
    const int g    = lane >> 2;
    const int tg   = lane & 3;
    const int mw   = warp * 16;

    for (int kc = 0; kc < DMODEL; kc += 32) {
        // A chunk: 128x32 = 512 uint4 -> 2 iters
        #pragma unroll
        for (int it = 0; it < 2; it++) {
            int i = tid + it * 256;
            int r = i >> 2, c8 = (i & 3) * 8;
            *(uint4*)&sAh[r][c8] = *(const uint4*)(Ahb + (size_t)r * DMODEL + kc + c8);
            *(uint4*)&sAl[r][c8] = *(const uint4*)(Alb + (size_t)r * DMODEL + kc + c8);
        }
        // B chunk: 64x32 = 256 uint4 -> 1 iter
        {
            int r = tid >> 2, c8 = (tid & 3) * 8;
            *(uint4*)&sBh[r][c8] = *(const uint4*)(Bhb + (size_t)r * DMODEL + kc + c8);
            *(uint4*)&sBl[r][c8] = *(const uint4*)(Blb + (size_t)r * DMODEL + kc + c8);
        }
        __syncthreads();

        #pragma unroll
        for (int ks = 0; ks < 2; ks++) {
            const int k0 = ks * 16;
            uint32_t ah0 = *(const uint32_t*)&sAh[mw + g    ][k0 + 2 * tg];
            uint32_t ah1 = *(const uint32_t*)&sAh[mw + 8 + g][k0 + 2 * tg];
            uint32_t ah2 = *(const uint32_t*)&sAh[mw + g    ][k0 + 8 + 2 * tg];
            uint32_t ah3 = *(const uint32_t*)&sAh[mw + 8 + g][k0 + 8 + 2 * tg];
            uint32_t al0 = *(const uint32_t*)&sAl[mw + g    ][k0 + 2 * tg];
            uint32_t al1 = *(const uint32_t*)&sAl[mw + 8 + g][k0 + 2 * tg];
            uint32_t al2 = *(const uint32_t*)&sAl[mw + g    ][k0 + 8 + 2 * tg];
            uint32_t al3 = *(const uint32_t*)&sAl[mw + 8 + g][k0 + 8 + 2 * tg];
            #pragma unroll
            for (int nt = 0; nt < 8; nt++) {
                uint32_t bh0 = *(const uint32_t*)&sBh[nt * 8 + g][k0 + 2 * tg];
                uint32_t bh1 = *(const uint32_t*)&sBh[nt * 8 + g][k0 + 8 + 2 * tg];
                uint32_t bl0 = *(const uint32_t*)&sBl[nt * 8 + g][k0 + 2 * tg];
                uint32_t bl1 = *(const uint32_t*)&sBl[nt * 8 + g][k0 + 8 + 2 * tg];
                mma_bf16(O[nt][0], O[nt][1], O[nt][2], O[nt][3],
                         ah0, ah1, ah2, ah3, bh0, bh1);
                mma_bf16(O[nt][0], O[nt][1], O[nt][2], O[nt][3],
                         ah0, ah1, ah2, ah3, bl0, bl1);
                mma_bf16(O[nt][0], O[nt][1], O[nt][2], O[nt][3],
                         al0, al1, al2, al3, bh0, bh1);
            }
        }
        __syncthreads();
    }
}

// QKV variant: grid (HEADS, ROWS/128); out fp32 [zh][n][64] + bias
__global__ __launch_bounds__(256) void gemm_bf3_qkv(
    const __nv_bfloat16* __restrict__ Ah, const __nv_bfloat16* __restrict__ Al,
    const __nv_bfloat16* __restrict__ Bh, const __nv_bfloat16* __restrict__ Bl,
    const float* __restrict__ bias, float* __restrict__ Out)
{
    const int h  = blockIdx.x;
    const int mb = blockIdx.y;

    float O[8][4] = {};
    gemm_bf3_core(Ah + (size_t)mb * 128 * DMODEL, Al + (size_t)mb * 128 * DMODEL,
                  Bh + (size_t)h * DK * DMODEL,   Bl + (size_t)h * DK * DMODEL, O);

    const int warp = threadIdx.x >> 5;
    const int lane = threadIdx.x & 31;
    const int g    = lane >> 2;
    const int tg   = lane & 3;
    const int row0 = mb * 128 + warp * 16 + g;
    const int row1 = row0 + 8;
    const int z0 = row0 >> 11, n0 = row0 & (NTOK - 1);
    const int z1 = row1 >> 11, n1 = row1 & (NTOK - 1);

    #pragma unroll
    for (int nt = 0; nt < 8; nt++) {
        int col = nt * 8 + 2 * tg;
        float b0 = bias[h * DK + col], b1 = bias[h * DK + col + 1];
        *(float2*)&Out[(((size_t)z0 * HEADS + h) * NTOK + n0) * DK + col] =
            make_float2(O[nt][0] + b0, O[nt][1] + b1);
        *(float2*)&Out[(((size_t)z1 * HEADS + h) * NTOK + n1) * DK + col] =
            make_float2(O[nt][2] + b0, O[nt][3] + b1);
    }
}

// Out-proj variant: grid (DMODEL/64, ROWS/128); reads split ctx, writes fp32 out
__global__ __launch_bounds__(256) void gemm_bf3_out(
    const __nv_bfloat16* __restrict__ Ah, const __nv_bfloat16* __restrict__ Al,
    const __nv_bfloat16* __restrict__ Bh, const __nv_bfloat16* __restrict__ Bl,
    float* __restrict__ Out)
{
    const int cb = blockIdx.x;
    const int mb = blockIdx.y;

    float O[8][4] = {};
    gemm_bf3_core(Ah + (size_t)mb * 128 * DMODEL, Al + (size_t)mb * 128 * DMODEL,
                  Bh + (size_t)cb * 64 * DMODEL,  Bl + (size_t)cb * 64 * DMODEL, O);

    const int warp = threadIdx.x >> 5;
    const int lane = threadIdx.x & 31;
    const int g    = lane >> 2;
    const int tg   = lane & 3;
    const int row0 = mb * 128 + warp * 16 + g;
    const int row1 = row0 + 8;

    #pragma unroll
    for (int nt = 0; nt < 8; nt++) {
        int col = cb * 64 + nt * 8 + 2 * tg;
        *(float2*)&Out[(size_t)row0 * DMODEL + col] = make_float2(O[nt][0], O[nt][1]);
        *(float2*)&Out[(size_t)row1 * DMODEL + col] = make_float2(O[nt][2], O[nt][3]);
    }
}

// ---------------------------------------------------------------------------
// V split + transpose: Vt[zh][dk][key] = split(V[zh][key][dk])
// grid = (NTOK/64, ZH), block = 128
// ---------------------------------------------------------------------------
__global__ __launch_bounds__(128) void split_vt_kernel(
    const float* __restrict__ V,
    __nv_bfloat16* __restrict__ Vth, __nv_bfloat16* __restrict__ Vtl)
{
    const int kt = blockIdx.x;
    const int zh = blockIdx.y;
    const int tid = threadIdx.x;
    __shared__ float tile[64][65];

    const float* src = V + (size_t)zh * NTOK * DK + (size_t)kt * 64 * DK;
    #pragma unroll
    for (int it = 0; it < 8; it++) {
        int i4 = tid + it * 128;
        int key = i4 >> 4;
        int d4 = (i4 & 15) * 4;
        float4 v = *(const float4*)(src + (size_t)key * DK + d4);
        tile[key][d4 + 0] = v.x; tile[key][d4 + 1] = v.y;
        tile[key][d4 + 2] = v.z; tile[key][d4 + 3] = v.w;
    }
    __syncthreads();
    #pragma unroll
    for (int it = 0; it < 32; it++) {
        int o = tid + it * 128;
        int dk = o >> 6;
        int key = o & 63;
        float x = tile[key][dk];
        __nv_bfloat16 h, l;
        split1(x, h, l);
        size_t idx = (size_t)zh * DK * NTOK + (size_t)dk * NTOK + kt * 64 + key;
        Vth[idx] = h;
        Vtl[idx] = l;
    }
}

// ---------------------------------------------------------------------------
// Flash attention with m16n8k16 bf16 MMA, 3-term hi/lo split.
// Block = 128 threads (4 warps), 64 queries/block. grid = (NTOK/64, ZH)
// Writes context pre-split into bf16 hi/lo for the out-proj MMA GEMM.
// ---------------------------------------------------------------------------
__global__ __launch_bounds__(128) void attn_mma(
    const float* __restrict__ Q,
    const __nv_bfloat16* __restrict__ Kh, const __nv_bfloat16* __restrict__ Kl,
    const __nv_bfloat16* __restrict__ Vth, const __nv_bfloat16* __restrict__ Vtl,
    const int* __restrict__ mask,
    __nv_bfloat16* __restrict__ Ch, __nv_bfloat16* __restrict__ Cl)
{
    const int qt   = blockIdx.x;
    const int zh   = blockIdx.y;
    const int z    = zh >> 4;
    const int h    = zh & 15;
    const int tid  = threadIdx.x;
    const int warp = tid >> 5;
    const int lane = tid & 31;
    const int g    = lane >> 2;
    const int tg   = lane & 3;

    __shared__ __align__(16) unsigned char smem_raw[4 * 64 * 72 * 2 + 256];
    typedef __nv_bfloat16(*tile_t)[72];
    tile_t sKh = (tile_t)(smem_raw);
    tile_t sKl = (tile_t)(smem_raw + 9216);
    tile_t sVh = (tile_t)(smem_raw + 18432);
    tile_t sVl = (tile_t)(smem_raw + 27648);
    int* smk   = (int*)(smem_raw + 36864);

    const size_t base  = (size_t)zh * NTOK * DK;
    const size_t baseT = (size_t)zh * DK * NTOK;

    {
        float4* dst = (float4*)smem_raw;
        const float4* src = (const float4*)(Q + base + (size_t)qt * 64 * DK);
        #pragma unroll
        for (int i = tid; i < 64 * DK / 4; i += 128) dst[i] = src[i];
    }
    __syncthreads();

    uint32_t Qh[4][4], Ql[4][4];
    {
        const float* sQ = (const float*)smem_raw;
        int r0 = warp * 16 + g;
        int r1 = r0 + 8;
        #pragma unroll
        for (int kk = 0; kk < 4; kk++) {
            int c = kk * 16 + 2 * tg;
            split2(SCALE * sQ[r0 * 64 + c],     SCALE * sQ[r0 * 64 + c + 1], Qh[kk][0], Ql[kk][0]);
            split2(SCALE * sQ[r1 * 64 + c],     SCALE * sQ[r1 * 64 + c + 1], Qh[kk][1], Ql[kk][1]);
            split2(SCALE * sQ[r0 * 64 + c + 8], SCALE * sQ[r0 * 64 + c + 9], Qh[kk][2], Ql[kk][2]);
            split2(SCALE * sQ[r1 * 64 + c + 8], SCALE * sQ[r1 * 64 + c + 9], Qh[kk][3], Ql[kk][3]);
        }
    }
    __syncthreads();

    float O[8][4];
    #pragma unroll
    for (int nt = 0; nt < 8; nt++)
        O[nt][0] = O[nt][1] = O[nt][2] = O[nt][3] = 0.f;
    float m0 = -1e30f, m1 = -1e30f, l0 = 0.f, l1 = 0.f;

    for (int kt = 0; kt < NTOK / 64; kt++) {
        {
            const __nv_bfloat16* gkh = Kh + base + (size_t)kt * 64 * DK;
            const __nv_bfloat16* gkl = Kl + base + (size_t)kt * 64 * DK;
            #pragma unroll
            for (int it = 0; it < 4; it++) {
                int i = tid + it * 128;
                int row = i >> 3;
                int c8 = (i & 7) * 8;
                *(uint4*)&sKh[row][c8] = *(const uint4*)(gkh + (size_t)row * DK + c8);
                *(uint4*)&sKl[row][c8] = *(const uint4*)(gkl + (size_t)row * DK + c8);
                *(uint4*)&sVh[row][c8] =
                    *(const uint4*)(Vth + baseT + (size_t)row * NTOK + kt * 64 + c8);
                *(uint4*)&sVl[row][c8] =
                    *(const uint4*)(Vtl + baseT + (size_t)row * NTOK + kt * 64 + c8);
            }
            if (tid < 64) smk[tid] = mask[z * NTOK + kt * 64 + tid];
        }
        __syncthreads();

        float S[8][4];
        #pragma unroll
        for (int nt = 0; nt < 8; nt++) {
            S[nt][0] = S[nt][1] = S[nt][2] = S[nt][3] = 0.f;
            #pragma unroll
            for (int kk = 0; kk < 4; kk++) {
                uint32_t bh0 = *(const uint32_t*)&sKh[nt * 8 + g][kk * 16 + 2 * tg];
                uint32_t bh1 = *(const uint32_t*)&sKh[nt * 8 + g][kk * 16 + 8 + 2 * tg];
                uint32_t bl0 = *(const uint32_t*)&sKl[nt * 8 + g][kk * 16 + 2 * tg];
                uint32_t bl1 = *(const uint32_t*)&sKl[nt * 8 + g][kk * 16 + 8 + 2 * tg];
                mma_bf16(S[nt][0], S[nt][1], S[nt][2], S[nt][3],
                         Qh[kk][0], Qh[kk][1], Qh[kk][2], Qh[kk][3], bh0, bh1);
                mma_bf16(S[nt][0], S[nt][1], S[nt][2], S[nt][3],
                         Qh[kk][0], Qh[kk][1], Qh[kk][2], Qh[kk][3], bl0, bl1);
                mma_bf16(S[nt][0], S[nt][1], S[nt][2], S[nt][3],
                         Ql[kk][0], Ql[kk][1], Ql[kk][2], Ql[kk][3], bh0, bh1);
            }
        }

        float mx0 = -1e30f, mx1 = -1e30f;
        #pragma unroll
        for (int nt = 0; nt < 8; nt++) {
            #pragma unroll
            for (int j = 0; j < 2; j++) {
                int key = nt * 8 + 2 * tg + j;
                bool ok = smk[key] != 0;
                float v0 = ok ? S[nt][j]     : -1e9f;
                float v1 = ok ? S[nt][2 + j] : -1e9f;
                S[nt][j] = v0; S[nt][2 + j] = v1;
                mx0 = fmaxf(mx0, v0); mx1 = fmaxf(mx1, v1);
            }
        }
        mx0 = fmaxf(mx0, __shfl_xor_sync(0xffffffffu, mx0, 1));
        mx0 = fmaxf(mx0, __shfl_xor_sync(0xffffffffu, mx0, 2));
        mx1 = fmaxf(mx1, __shfl_xor_sync(0xffffffffu, mx1, 1));
        mx1 = fmaxf(mx1, __shfl_xor_sync(0xffffffffu, mx1, 2));

        float mn0 = fmaxf(m0, mx0), mn1 = fmaxf(m1, mx1);
        float corr0 = __expf(m0 - mn0), corr1 = __expf(m1 - mn1);
        m0 = mn0; m1 = mn1;

        float ls0 = 0.f, ls1 = 0.f;
        #pragma unroll
        for (int nt = 0; nt < 8; nt++) {
            S[nt][0] = __expf(S[nt][0] - m0); ls0 += S[nt][0];
            S[nt][1] = __expf(S[nt][1] - m0); ls0 += S[nt][1];
            S[nt][2] = __expf(S[nt][2] - m1); ls1 += S[nt][2];
            S[nt][3] = __expf(S[nt][3] - m1); ls1 += S[nt][3];
        }
        ls0 += __shfl_xor_sync(0xffffffffu, ls0, 1);
        ls0 += __shfl_xor_sync(0xffffffffu, ls0, 2);
        ls1 += __shfl_xor_sync(0xffffffffu, ls1, 1);
        ls1 += __shfl_xor_sync(0xffffffffu, ls1, 2);
        l0 = l0 * corr0 + ls0;
        l1 = l1 * corr1 + ls1;

        #pragma unroll
        for (int nt = 0; nt < 8; nt++) {
            O[nt][0] *= corr0; O[nt][1] *= corr0;
            O[nt][2] *= corr1; O[nt][3] *= corr1;
        }

        #pragma unroll
        for (int kk = 0; kk < 4; kk++) {
            uint32_t ah[4], al[4];
            split2(S[2 * kk][0],     S[2 * kk][1],     ah[0], al[0]);
            split2(S[2 * kk][2],     S[2 * kk][3],     ah[1], al[1]);
            split2(S[2 * kk + 1][0], S[2 * kk + 1][1], ah[2], al[2]);
            split2(S[2 * kk + 1][2], S[2 * kk + 1][3], ah[3], al[3]);
            #pragma unroll
            for (int nt = 0; nt < 8; nt++) {
                uint32_t bh0 = *(const uint32_t*)&sVh[nt * 8 + g][kk * 16 + 2 * tg];
                uint32_t bh1 = *(const uint32_t*)&sVh[nt * 8 + g][kk * 16 + 8 + 2 * tg];
                uint32_t bl0 = *(const uint32_t*)&sVl[nt * 8 + g][kk * 16 + 2 * tg];
                uint32_t bl1 = *(const uint32_t*)&sVl[nt * 8 + g][kk * 16 + 8 + 2 * tg];
                mma_bf16(O[nt][0], O[nt][1], O[nt][2], O[nt][3],
                         ah[0], ah[1], ah[2], ah[3], bh0, bh1);
                mma_bf16(O[nt][0], O[nt][1], O[nt][2], O[nt][3],
                         ah[0], ah[1], ah[2], ah[3], bl0, bl1);
                mma_bf16(O[nt][0], O[nt][1], O[nt][2], O[nt][3],
                         al[0], al[1], al[2], al[3], bh0, bh1);
            }
        }
        __syncthreads();
    }

    // epilogue: normalize, zero invalid queries, write SPLIT ctx
    const int tok0 = qt * 64 + warp * 16 + g;
    const int tok1 = tok0 + 8;
    const int qv0 = mask[z * NTOK + tok0];
    const int qv1 = mask[z * NTOK + tok1];
    const float inv0 = (qv0 && l0 > 0.f) ? 1.0f / l0 : 0.f;
    const float inv1 = (qv1 && l1 > 0.f) ? 1.0f / l1 : 0.f;

    #pragma unroll
    for (int nt = 0; nt < 8; nt++) {
        int dk = nt * 8 + 2 * tg;
        size_t i0 = ((size_t)(z * NTOK + tok0)) * DMODEL + h * DK + dk;
        size_t i1 = ((size_t)(z * NTOK + tok1)) * DMODEL + h * DK + dk;
        uint32_t hh, ll;
        split2(O[nt][0] * inv0, O[nt][1] * inv0, hh, ll);
        *(uint32_t*)&Ch[i0] = hh; *(uint32_t*)&Cl[i0] = ll;
        split2(O[nt][2] * inv1, O[nt][3] * inv1, hh, ll);
        *(uint32_t*)&Ch[i1] = hh; *(uint32_t*)&Cl[i1] = ll;
    }
}

// ---------------------------------------------------------------------------
// K split (fixed size)
// ---------------------------------------------------------------------------
__global__ void split_k_kernel(const float* __restrict__ in,
                               __nv_bfloat16* __restrict__ hi,
                               __nv_bfloat16* __restrict__ lo)
{
    const int n = ZH * NTOK * DK;
    for (int i = blockIdx.x * blockDim.x + threadIdx.x; i < n;
         i += gridDim.x * blockDim.x) {
        float x = in[i];
        __nv_bfloat16 h, l;
        split1(x, h, l);
        hi[i] = h;
        lo[i] = l;
    }
}

// ---------------------------------------------------------------------------
// Host entry
// ---------------------------------------------------------------------------
extern "C" void kernel_launch(void* const* d_in, const int* in_sizes, int n_in,
                              void* d_out, int out_size)
{
    const float* x     = (const float*)d_in[0];
    const int*   mask  = (const int*)  d_in[1];
    const float* qproj = (const float*)d_in[2];
    const float* kproj = (const float*)d_in[3];
    const float* vproj = (const float*)d_in[4];
    const float* qbias = (const float*)d_in[5];
    const float* kbias = (const float*)d_in[6];
    const float* vbias = (const float*)d_in[7];
    const float* outw  = (const float*)d_in[8];
    float* out = (float*)d_out;

    float *Q, *K, *V;
    __nv_bfloat16 *Xh, *Xl, *BQh, *BQl, *BKh, *BKl, *BVh, *BVl, *Wh, *Wl;
    __nv_bfloat16 *Ch, *Cl, *Kh, *Kl, *Vth, *Vtl;
    cudaGetSymbolAddress((void**)&Q,   g_Q);
    cudaGetSymbolAddress((void**)&K,   g_K);
    cudaGetSymbolAddress((void**)&V,   g_V);
    cudaGetSymbolAddress((void**)&Xh,  g_Xh);
    cudaGetSymbolAddress((void**)&Xl,  g_Xl);
    cudaGetSymbolAddress((void**)&BQh, g_BQh);
    cudaGetSymbolAddress((void**)&BQl, g_BQl);
    cudaGetSymbolAddress((void**)&BKh, g_BKh);
    cudaGetSymbolAddress((void**)&BKl, g_BKl);
    cudaGetSymbolAddress((void**)&BVh, g_BVh);
    cudaGetSymbolAddress((void**)&BVl, g_BVl);
    cudaGetSymbolAddress((void**)&Wh,  g_Wh);
    cudaGetSymbolAddress((void**)&Wl,  g_Wl);
    cudaGetSymbolAddress((void**)&Ch,  g_Ch);
    cudaGetSymbolAddress((void**)&Cl,  g_Cl);
    cudaGetSymbolAddress((void**)&Kh,  g_Kh);
    cudaGetSymbolAddress((void**)&Kl,  g_Kl);
    cudaGetSymbolAddress((void**)&Vth, g_Vth);
    cudaGetSymbolAddress((void**)&Vtl, g_Vtl);

    // input splits
    split_any_kernel<<<2048, 256>>>(x, Xh, Xl, ROWS * DMODEL);
    split_proj_kernel<<<dim3(DMODEL / 64, HEADS), 256>>>(qproj, BQh, BQl);
    split_proj_kernel<<<dim3(DMODEL / 64, HEADS), 256>>>(kproj, BKh, BKl);
    split_proj_kernel<<<dim3(DMODEL / 64, HEADS), 256>>>(vproj, BVh, BVl);
    split_any_kernel<<<1024, 256>>>(outw, Wh, Wl, DMODEL * DMODEL);

    // QKV projections (tensor-core)
    dim3 gq(HEADS, ROWS / 128);
    gemm_bf3_qkv<<<gq, 256>>>(Xh, Xl, BQh, BQl, qbias, Q);
    gemm_bf3_qkv<<<gq, 256>>>(Xh, Xl, BKh, BKl, kbias, K);
    gemm_bf3_qkv<<<gq, 256>>>(Xh, Xl, BVh, BVl, vbias, V);

    // attention-side splits
    split_k_kernel<<<2048, 256>>>(K, Kh, Kl);
    split_vt_kernel<<<dim3(NTOK / 64, ZH), 128>>>(V, Vth, Vtl);

    // attention (tensor-core), writes split ctx
    attn_mma<<<dim3(NTOK / 64, ZH), 128>>>(Q, Kh, Kl, Vth, Vtl, mask, Ch, Cl);

    // output projection (tensor-core)
    gemm_bf3_out<<<dim3(DMODEL / 64, ROWS / 128), 256>>>(Ch, Cl, Wh, Wl, out);
}

// round 7
// speedup vs baseline: 4.2950x; 1.1690x over previous
#include <cuda_runtime.h>
#include <cuda_bf16.h>
#include <cstdint>

// Problem constants
#define ZB     2
#define NTOK   2048
#define DMODEL 1024
#define HEADS  16
#define DK     64
#define ROWS   (ZB * NTOK)          // 4096
#define SCALE  0.125f               // DK^-0.5
#define ZH     (ZB * HEADS)         // 32

// ---------------------------------------------------------------------------
// Device scratch (no runtime allocation allowed)
// ---------------------------------------------------------------------------
__device__ __nv_bfloat16 g_Xh[ROWS * DMODEL];   // x split
__device__ __nv_bfloat16 g_Xl[ROWS * DMODEL];
__device__ __nv_bfloat16 g_BQh[HEADS * DK * DMODEL];  // proj split, [h][n][k]
__device__ __nv_bfloat16 g_BQl[HEADS * DK * DMODEL];
__device__ __nv_bfloat16 g_BKh[HEADS * DK * DMODEL];
__device__ __nv_bfloat16 g_BKl[HEADS * DK * DMODEL];
__device__ __nv_bfloat16 g_BVh[HEADS * DK * DMODEL];
__device__ __nv_bfloat16 g_BVl[HEADS * DK * DMODEL];
__device__ __nv_bfloat16 g_Wh[DMODEL * DMODEL]; // out_w split ([n][k] = native)
__device__ __nv_bfloat16 g_Wl[DMODEL * DMODEL];
__device__ __nv_bfloat16 g_Ch[ROWS * DMODEL];   // ctx split (attention output)
__device__ __nv_bfloat16 g_Cl[ROWS * DMODEL];

// pre-split QKV (written directly by GEMM epilogues)
__device__ __nv_bfloat16 g_Qh[ZH * NTOK * DK];  // [zh][n][dk], SCALE folded
__device__ __nv_bfloat16 g_Ql[ZH * NTOK * DK];
__device__ __nv_bfloat16 g_Kh[ZH * NTOK * DK];  // [zh][key][dk]
__device__ __nv_bfloat16 g_Kl[ZH * NTOK * DK];
__device__ __nv_bfloat16 g_Vth[ZH * DK * NTOK]; // transposed: [zh][dk][key]
__device__ __nv_bfloat16 g_Vtl[ZH * DK * NTOK];

// ---------------------------------------------------------------------------
// helpers
// ---------------------------------------------------------------------------
__device__ __forceinline__ uint32_t packb(__nv_bfloat16 x, __nv_bfloat16 y) {
    return (uint32_t)__bfloat16_as_ushort(x) |
           ((uint32_t)__bfloat16_as_ushort(y) << 16);
}
__device__ __forceinline__ void split1(float x, __nv_bfloat16& h, __nv_bfloat16& l) {
    h = __float2bfloat16(x);
    l = __float2bfloat16(x - __bfloat162float(h));
}
__device__ __forceinline__ void split2(float x, float y, uint32_t& hi, uint32_t& lo) {
    __nv_bfloat16 xh, xl, yh, yl;
    split1(x, xh, xl);
    split1(y, yh, yl);
    hi = packb(xh, yh);
    lo = packb(xl, yl);
}

__device__ __forceinline__ void mma_bf16(
    float& c0, float& c1, float& c2, float& c3,
    uint32_t a0, uint32_t a1, uint32_t a2, uint32_t a3,
    uint32_t b0, uint32_t b1)
{
    asm volatile(
        "mma.sync.aligned.m16n8k16.row.col.f32.bf16.bf16.f32 "
        "{%0,%1,%2,%3},{%4,%5,%6,%7},{%8,%9},{%0,%1,%2,%3};\n"
        : "+f"(c0), "+f"(c1), "+f"(c2), "+f"(c3)
        : "r"(a0), "r"(a1), "r"(a2), "r"(a3), "r"(b0), "r"(b1));
}

__device__ __forceinline__ void cp_async16(uint32_t dst, const void* src) {
    asm volatile("cp.async.cg.shared.global [%0], [%1], 16;" :: "r"(dst), "l"(src));
}
__device__ __forceinline__ void cp_async4(uint32_t dst, const void* src) {
    asm volatile("cp.async.ca.shared.global [%0], [%1], 4;" :: "r"(dst), "l"(src));
}
__device__ __forceinline__ void cp_commit() {
    asm volatile("cp.async.commit_group;");
}
template <int N>
__device__ __forceinline__ void cp_wait() {
    asm volatile("cp.async.wait_group %0;" :: "n"(N));
}

// ---------------------------------------------------------------------------
// Elementwise split: fp32 -> (hi, lo) bf16
// ---------------------------------------------------------------------------
__global__ void split_any_kernel(const float* __restrict__ in,
                                 __nv_bfloat16* __restrict__ hi,
                                 __nv_bfloat16* __restrict__ lo, int n)
{
    for (int i = blockIdx.x * blockDim.x + threadIdx.x; i < n;
         i += gridDim.x * blockDim.x) {
        float x = in[i];
        __nv_bfloat16 h, l;
        split1(x, h, l);
        hi[i] = h;
        lo[i] = l;
    }
}

// ---------------------------------------------------------------------------
// Proj split + transpose: proj[h][d][n] (fp32) -> B[h][n][d] hi/lo (bf16)
// grid = (DMODEL/64, HEADS), block = 256
// ---------------------------------------------------------------------------
__global__ __launch_bounds__(256) void split_proj_kernel(
    const float* __restrict__ proj,
    __nv_bfloat16* __restrict__ Bh, __nv_bfloat16* __restrict__ Bl)
{
    const int dt = blockIdx.x;
    const int h  = blockIdx.y;
    const int tid = threadIdx.x;
    __shared__ float tile[64][65];

    const float* src = proj + ((size_t)h * DMODEL + dt * 64) * DK;
    #pragma unroll
    for (int it = 0; it < 4; it++) {
        int i4 = tid + it * 256;
        int r  = i4 >> 4;
        int c4 = (i4 & 15) * 4;
        float4 v = *(const float4*)(src + (size_t)r * DK + c4);
        tile[r][c4 + 0] = v.x; tile[r][c4 + 1] = v.y;
        tile[r][c4 + 2] = v.z; tile[r][c4 + 3] = v.w;
    }
    __syncthreads();
    #pragma unroll
    for (int it = 0; it < 16; it++) {
        int o = tid + it * 256;
        int n = o >> 6;
        int j = o & 63;
        float x = tile[j][n];
        __nv_bfloat16 hh, ll;
        split1(x, hh, ll);
        size_t idx = ((size_t)h * DK + n) * DMODEL + dt * 64 + j;
        Bh[idx] = hh;
        Bl[idx] = ll;
    }
}

// ---------------------------------------------------------------------------
// bf16x3 MMA GEMM core: 128x64 block tile, K in chunks of 32. 8 warps.
// ---------------------------------------------------------------------------
__device__ __forceinline__ void gemm_bf3_core(
    const __nv_bfloat16* __restrict__ Ahb, const __nv_bfloat16* __restrict__ Alb,
    const __nv_bfloat16* __restrict__ Bhb, const __nv_bfloat16* __restrict__ Blb,
    float O[8][4])
{
    __shared__ __nv_bfloat16 sAh[128][40], sAl[128][40];
    __shared__ __nv_bfloat16 sBh[64][40],  sBl[64][40];

    const int tid  = threadIdx.x;
    const int warp = tid >> 5;
    const int lane = tid & 31;
    const int g    = lane >> 2;
    const int tg   = lane & 3;
    const int mw   = warp * 16;

    for (int kc = 0; kc < DMODEL; kc += 32) {
        #pragma unroll
        for (int it = 0; it < 2; it++) {
            int i = tid + it * 256;
            int r = i >> 2, c8 = (i & 3) * 8;
            *(uint4*)&sAh[r][c8] = *(const uint4*)(Ahb + (size_t)r * DMODEL + kc + c8);
            *(uint4*)&sAl[r][c8] = *(const uint4*)(Alb + (size_t)r * DMODEL + kc + c8);
        }
        {
            int r = tid >> 2, c8 = (tid & 3) * 8;
            *(uint4*)&sBh[r][c8] = *(const uint4*)(Bhb + (size_t)r * DMODEL + kc + c8);
            *(uint4*)&sBl[r][c8] = *(const uint4*)(Blb + (size_t)r * DMODEL + kc + c8);
        }
        __syncthreads();

        #pragma unroll
        for (int ks = 0; ks < 2; ks++) {
            const int k0 = ks * 16;
            uint32_t ah0 = *(const uint32_t*)&sAh[mw + g    ][k0 + 2 * tg];
            uint32_t ah1 = *(const uint32_t*)&sAh[mw + 8 + g][k0 + 2 * tg];
            uint32_t ah2 = *(const uint32_t*)&sAh[mw + g    ][k0 + 8 + 2 * tg];
            uint32_t ah3 = *(const uint32_t*)&sAh[mw + 8 + g][k0 + 8 + 2 * tg];
            uint32_t al0 = *(const uint32_t*)&sAl[mw + g    ][k0 + 2 * tg];
            uint32_t al1 = *(const uint32_t*)&sAl[mw + 8 + g][k0 + 2 * tg];
            uint32_t al2 = *(const uint32_t*)&sAl[mw + g    ][k0 + 8 + 2 * tg];
            uint32_t al3 = *(const uint32_t*)&sAl[mw + 8 + g][k0 + 8 + 2 * tg];
            #pragma unroll
            for (int nt = 0; nt < 8; nt++) {
                uint32_t bh0 = *(const uint32_t*)&sBh[nt * 8 + g][k0 + 2 * tg];
                uint32_t bh1 = *(const uint32_t*)&sBh[nt * 8 + g][k0 + 8 + 2 * tg];
                uint32_t bl0 = *(const uint32_t*)&sBl[nt * 8 + g][k0 + 2 * tg];
                uint32_t bl1 = *(const uint32_t*)&sBl[nt * 8 + g][k0 + 8 + 2 * tg];
                mma_bf16(O[nt][0], O[nt][1], O[nt][2], O[nt][3],
                         ah0, ah1, ah2, ah3, bh0, bh1);
                mma_bf16(O[nt][0], O[nt][1], O[nt][2], O[nt][3],
                         ah0, ah1, ah2, ah3, bl0, bl1);
                mma_bf16(O[nt][0], O[nt][1], O[nt][2], O[nt][3],
                         al0, al1, al2, al3, bh0, bh1);
            }
        }
        __syncthreads();
    }
}

// Q projection: writes pre-split, pre-scaled Qh/Ql [zh][n][dk]
__global__ __launch_bounds__(256) void gemm_bf3_q(
    const __nv_bfloat16* __restrict__ Ah, const __nv_bfloat16* __restrict__ Al,
    const __nv_bfloat16* __restrict__ Bh, const __nv_bfloat16* __restrict__ Bl,
    const float* __restrict__ bias,
    __nv_bfloat16* __restrict__ Qh, __nv_bfloat16* __restrict__ Ql)
{
    const int h  = blockIdx.x;
    const int mb = blockIdx.y;
    float O[8][4] = {};
    gemm_bf3_core(Ah + (size_t)mb * 128 * DMODEL, Al + (size_t)mb * 128 * DMODEL,
                  Bh + (size_t)h * DK * DMODEL,   Bl + (size_t)h * DK * DMODEL, O);

    const int warp = threadIdx.x >> 5, lane = threadIdx.x & 31;
    const int g = lane >> 2, tg = lane & 3;
    const int row0 = mb * 128 + warp * 16 + g, row1 = row0 + 8;
    const int z = row0 >> 11, n0 = row0 & (NTOK - 1), n1 = row1 & (NTOK - 1);
    const int zh = z * HEADS + h;

    #pragma unroll
    for (int nt = 0; nt < 8; nt++) {
        int col = nt * 8 + 2 * tg;
        float b0 = bias[h * DK + col], b1 = bias[h * DK + col + 1];
        uint32_t hh, ll;
        size_t i0 = ((size_t)zh * NTOK + n0) * DK + col;
        size_t i1 = ((size_t)zh * NTOK + n1) * DK + col;
        split2((O[nt][0] + b0) * SCALE, (O[nt][1] + b1) * SCALE, hh, ll);
        *(uint32_t*)&Qh[i0] = hh; *(uint32_t*)&Ql[i0] = ll;
        split2((O[nt][2] + b0) * SCALE, (O[nt][3] + b1) * SCALE, hh, ll);
        *(uint32_t*)&Qh[i1] = hh; *(uint32_t*)&Ql[i1] = ll;
    }
}

// K projection: writes pre-split Kh/Kl [zh][key][dk]
__global__ __launch_bounds__(256) void gemm_bf3_k(
    const __nv_bfloat16* __restrict__ Ah, const __nv_bfloat16* __restrict__ Al,
    const __nv_bfloat16* __restrict__ Bh, const __nv_bfloat16* __restrict__ Bl,
    const float* __restrict__ bias,
    __nv_bfloat16* __restrict__ Kh, __nv_bfloat16* __restrict__ Kl)
{
    const int h  = blockIdx.x;
    const int mb = blockIdx.y;
    float O[8][4] = {};
    gemm_bf3_core(Ah + (size_t)mb * 128 * DMODEL, Al + (size_t)mb * 128 * DMODEL,
                  Bh + (size_t)h * DK * DMODEL,   Bl + (size_t)h * DK * DMODEL, O);

    const int warp = threadIdx.x >> 5, lane = threadIdx.x & 31;
    const int g = lane >> 2, tg = lane & 3;
    const int row0 = mb * 128 + warp * 16 + g, row1 = row0 + 8;
    const int z = row0 >> 11, n0 = row0 & (NTOK - 1), n1 = row1 & (NTOK - 1);
    const int zh = z * HEADS + h;

    #pragma unroll
    for (int nt = 0; nt < 8; nt++) {
        int col = nt * 8 + 2 * tg;
        float b0 = bias[h * DK + col], b1 = bias[h * DK + col + 1];
        uint32_t hh, ll;
        size_t i0 = ((size_t)zh * NTOK + n0) * DK + col;
        size_t i1 = ((size_t)zh * NTOK + n1) * DK + col;
        split2(O[nt][0] + b0, O[nt][1] + b1, hh, ll);
        *(uint32_t*)&Kh[i0] = hh; *(uint32_t*)&Kl[i0] = ll;
        split2(O[nt][2] + b0, O[nt][3] + b1, hh, ll);
        *(uint32_t*)&Kh[i1] = hh; *(uint32_t*)&Kl[i1] = ll;
    }
}

// V projection: writes pre-split TRANSPOSED Vth/Vtl [zh][dk][key]
__global__ __launch_bounds__(256) void gemm_bf3_v(
    const __nv_bfloat16* __restrict__ Ah, const __nv_bfloat16* __restrict__ Al,
    const __nv_bfloat16* __restrict__ Bh, const __nv_bfloat16* __restrict__ Bl,
    const float* __restrict__ bias,
    __nv_bfloat16* __restrict__ Vth, __nv_bfloat16* __restrict__ Vtl)
{
    const int h  = blockIdx.x;
    const int mb = blockIdx.y;
    float O[8][4] = {};
    gemm_bf3_core(Ah + (size_t)mb * 128 * DMODEL, Al + (size_t)mb * 128 * DMODEL,
                  Bh + (size_t)h * DK * DMODEL,   Bl + (size_t)h * DK * DMODEL, O);

    const int warp = threadIdx.x >> 5, lane = threadIdx.x & 31;
    const int g = lane >> 2, tg = lane & 3;
    const int row0 = mb * 128 + warp * 16 + g, row1 = row0 + 8;
    const int z = row0 >> 11, n0 = row0 & (NTOK - 1), n1 = row1 & (NTOK - 1);
    const size_t baseT = (size_t)(z * HEADS + h) * DK * NTOK;

    #pragma unroll
    for (int nt = 0; nt < 8; nt++) {
        int col = nt * 8 + 2 * tg;
        float b0 = bias[h * DK + col], b1 = bias[h * DK + col + 1];
        #pragma unroll
        for (int j = 0; j < 2; j++) {
            float v0 = O[nt][j]     + (j ? b1 : b0);   // row0, col+j
            float v1 = O[nt][2 + j] + (j ? b1 : b0);   // row1, col+j
            __nv_bfloat16 hh, ll;
            split1(v0, hh, ll);
            Vth[baseT + (size_t)(col + j) * NTOK + n0] = hh;
            Vtl[baseT + (size_t)(col + j) * NTOK + n0] = ll;
            split1(v1, hh, ll);
            Vth[baseT + (size_t)(col + j) * NTOK + n1] = hh;
            Vtl[baseT + (size_t)(col + j) * NTOK + n1] = ll;
        }
    }
}

// ---------------------------------------------------------------------------
// Flash attention: bf16x3 MMA + cp.async 2-stage pipelined K/V tiles.
// Block = 128 threads (4 warps), 64 queries/block. grid = (NTOK/64, ZH)
// Dynamic SMEM: 2 stages x (4 tiles [64][72] bf16 + 64-int mask) = 74240 B
// ---------------------------------------------------------------------------
#define TILE_B      9216        // 64 * 72 * 2
#define STAGE_B     37120       // 4*TILE_B + 256
#define OFF_KH      0
#define OFF_KL      (TILE_B)
#define OFF_VH      (2 * TILE_B)
#define OFF_VL      (3 * TILE_B)
#define OFF_MK      (4 * TILE_B)

extern __shared__ unsigned char smem_dyn[];

__global__ __launch_bounds__(128) void attn_mma(
    const __nv_bfloat16* __restrict__ Qh_g, const __nv_bfloat16* __restrict__ Ql_g,
    const __nv_bfloat16* __restrict__ Kh_g, const __nv_bfloat16* __restrict__ Kl_g,
    const __nv_bfloat16* __restrict__ Vth_g, const __nv_bfloat16* __restrict__ Vtl_g,
    const int* __restrict__ mask,
    __nv_bfloat16* __restrict__ Ch, __nv_bfloat16* __restrict__ Cl)
{
    const int qt   = blockIdx.x;
    const int zh   = blockIdx.y;
    const int z    = zh >> 4;
    const int h    = zh & 15;
    const int tid  = threadIdx.x;
    const int warp = tid >> 5;
    const int lane = tid & 31;
    const int g    = lane >> 2;
    const int tg   = lane & 3;

    typedef __nv_bfloat16(*tile_t)[72];
    const size_t base  = (size_t)zh * NTOK * DK;
    const size_t baseT = (size_t)zh * DK * NTOK;
    const uint32_t smem_u32 = (uint32_t)__cvta_generic_to_shared(smem_dyn);

    // per-thread tile-load coordinates (4 uint4 rows per array)
    const int lrow[4] = { tid >> 3, (tid + 128) >> 3, (tid + 256) >> 3, (tid + 384) >> 3 };
    const int lc8 = (tid & 7) * 8;

    // ---- stage Q hi/lo tiles into stage-0 smem, extract fragments ----
    {
        tile_t sQh = (tile_t)(smem_dyn + OFF_KH);
        tile_t sQl = (tile_t)(smem_dyn + OFF_KL);
        const __nv_bfloat16* gq_h = Qh_g + base + (size_t)qt * 64 * DK;
        const __nv_bfloat16* gq_l = Ql_g + base + (size_t)qt * 64 * DK;
        #pragma unroll
        for (int it = 0; it < 4; it++) {
            int row = lrow[it];
            *(uint4*)&sQh[row][lc8] = *(const uint4*)(gq_h + (size_t)row * DK + lc8);
            *(uint4*)&sQl[row][lc8] = *(const uint4*)(gq_l + (size_t)row * DK + lc8);
        }
    }
    __syncthreads();

    uint32_t Qh[4][4], Ql[4][4];
    {
        tile_t sQh = (tile_t)(smem_dyn + OFF_KH);
        tile_t sQl = (tile_t)(smem_dyn + OFF_KL);
        int r0 = warp * 16 + g, r1 = r0 + 8;
        #pragma unroll
        for (int kk = 0; kk < 4; kk++) {
            int c = kk * 16 + 2 * tg;
            Qh[kk][0] = *(const uint32_t*)&sQh[r0][c];
            Qh[kk][1] = *(const uint32_t*)&sQh[r1][c];
            Qh[kk][2] = *(const uint32_t*)&sQh[r0][c + 8];
            Qh[kk][3] = *(const uint32_t*)&sQh[r1][c + 8];
            Ql[kk][0] = *(const uint32_t*)&sQl[r0][c];
            Ql[kk][1] = *(const uint32_t*)&sQl[r1][c];
            Ql[kk][2] = *(const uint32_t*)&sQl[r0][c + 8];
            Ql[kk][3] = *(const uint32_t*)&sQl[r1][c + 8];
        }
    }
    __syncthreads();

    // ---- tile issuer (cp.async) ----
    auto issue_tile = [&](int kt, int stage) {
        const uint32_t sb = smem_u32 + stage * STAGE_B;
        const __nv_bfloat16* gkh = Kh_g + base + (size_t)kt * 64 * DK;
        const __nv_bfloat16* gkl = Kl_g + base + (size_t)kt * 64 * DK;
        const __nv_bfloat16* gvh = Vth_g + baseT + kt * 64;
        const __nv_bfloat16* gvl = Vtl_g + baseT + kt * 64;
        #pragma unroll
        for (int it = 0; it < 4; it++) {
            int row = lrow[it];
            uint32_t rowoff = row * 144 + lc8 * 2;
            cp_async16(sb + OFF_KH + rowoff, gkh + (size_t)row * DK + lc8);
            cp_async16(sb + OFF_KL + rowoff, gkl + (size_t)row * DK + lc8);
            cp_async16(sb + OFF_VH + rowoff, gvh + (size_t)row * NTOK + lc8);
            cp_async16(sb + OFF_VL + rowoff, gvl + (size_t)row * NTOK + lc8);
        }
        if (tid < 64)
            cp_async4(sb + OFF_MK + tid * 4, mask + z * NTOK + kt * 64 + tid);
    };

    float O[8][4];
    #pragma unroll
    for (int nt = 0; nt < 8; nt++)
        O[nt][0] = O[nt][1] = O[nt][2] = O[nt][3] = 0.f;
    float m0 = -1e30f, m1 = -1e30f, l0 = 0.f, l1 = 0.f;

    issue_tile(0, 0);
    cp_commit();

    for (int kt = 0; kt < NTOK / 64; kt++) {
        const int cur = kt & 1;
        if (kt + 1 < NTOK / 64) {
            issue_tile(kt + 1, cur ^ 1);
            cp_commit();
            cp_wait<1>();
        } else {
            cp_wait<0>();
        }
        __syncthreads();

        unsigned char* sb = smem_dyn + cur * STAGE_B;
        tile_t sKh = (tile_t)(sb + OFF_KH);
        tile_t sKl = (tile_t)(sb + OFF_KL);
        tile_t sVh = (tile_t)(sb + OFF_VH);
        tile_t sVl = (tile_t)(sb + OFF_VL);
        int*   smk = (int*)(sb + OFF_MK);

        // ---- S = Q x K^T (bf16x3) ----
        float S[8][4];
        #pragma unroll
        for (int nt = 0; nt < 8; nt++) {
            S[nt][0] = S[nt][1] = S[nt][2] = S[nt][3] = 0.f;
            #pragma unroll
            for (int kk = 0; kk < 4; kk++) {
                uint32_t bh0 = *(const uint32_t*)&sKh[nt * 8 + g][kk * 16 + 2 * tg];
                uint32_t bh1 = *(const uint32_t*)&sKh[nt * 8 + g][kk * 16 + 8 + 2 * tg];
                uint32_t bl0 = *(const uint32_t*)&sKl[nt * 8 + g][kk * 16 + 2 * tg];
                uint32_t bl1 = *(const uint32_t*)&sKl[nt * 8 + g][kk * 16 + 8 + 2 * tg];
                mma_bf16(S[nt][0], S[nt][1], S[nt][2], S[nt][3],
                         Qh[kk][0], Qh[kk][1], Qh[kk][2], Qh[kk][3], bh0, bh1);
                mma_bf16(S[nt][0], S[nt][1], S[nt][2], S[nt][3],
                         Qh[kk][0], Qh[kk][1], Qh[kk][2], Qh[kk][3], bl0, bl1);
                mma_bf16(S[nt][0], S[nt][1], S[nt][2], S[nt][3],
                         Ql[kk][0], Ql[kk][1], Ql[kk][2], Ql[kk][3], bh0, bh1);
            }
        }

        // ---- mask + online softmax ----
        float mx0 = -1e30f, mx1 = -1e30f;
        #pragma unroll
        for (int nt = 0; nt < 8; nt++) {
            #pragma unroll
            for (int j = 0; j < 2; j++) {
                int key = nt * 8 + 2 * tg + j;
                bool ok = smk[key] != 0;
                float v0 = ok ? S[nt][j]     : -1e9f;
                float v1 = ok ? S[nt][2 + j] : -1e9f;
                S[nt][j] = v0; S[nt][2 + j] = v1;
                mx0 = fmaxf(mx0, v0); mx1 = fmaxf(mx1, v1);
            }
        }
        mx0 = fmaxf(mx0, __shfl_xor_sync(0xffffffffu, mx0, 1));
        mx0 = fmaxf(mx0, __shfl_xor_sync(0xffffffffu, mx0, 2));
        mx1 = fmaxf(mx1, __shfl_xor_sync(0xffffffffu, mx1, 1));
        mx1 = fmaxf(mx1, __shfl_xor_sync(0xffffffffu, mx1, 2));

        float mn0 = fmaxf(m0, mx0), mn1 = fmaxf(m1, mx1);
        float corr0 = __expf(m0 - mn0), corr1 = __expf(m1 - mn1);
        m0 = mn0; m1 = mn1;

        float ls0 = 0.f, ls1 = 0.f;
        #pragma unroll
        for (int nt = 0; nt < 8; nt++) {
            S[nt][0] = __expf(S[nt][0] - m0); ls0 += S[nt][0];
            S[nt][1] = __expf(S[nt][1] - m0); ls0 += S[nt][1];
            S[nt][2] = __expf(S[nt][2] - m1); ls1 += S[nt][2];
            S[nt][3] = __expf(S[nt][3] - m1); ls1 += S[nt][3];
        }
        ls0 += __shfl_xor_sync(0xffffffffu, ls0, 1);
        ls0 += __shfl_xor_sync(0xffffffffu, ls0, 2);
        ls1 += __shfl_xor_sync(0xffffffffu, ls1, 1);
        ls1 += __shfl_xor_sync(0xffffffffu, ls1, 2);
        l0 = l0 * corr0 + ls0;
        l1 = l1 * corr1 + ls1;

        #pragma unroll
        for (int nt = 0; nt < 8; nt++) {
            O[nt][0] *= corr0; O[nt][1] *= corr0;
            O[nt][2] *= corr1; O[nt][3] *= corr1;
        }

        // ---- O += P x V (bf16x3) ----
        #pragma unroll
        for (int kk = 0; kk < 4; kk++) {
            uint32_t ah[4], al[4];
            split2(S[2 * kk][0],     S[2 * kk][1],     ah[0], al[0]);
            split2(S[2 * kk][2],     S[2 * kk][3],     ah[1], al[1]);
            split2(S[2 * kk + 1][0], S[2 * kk + 1][1], ah[2], al[2]);
            split2(S[2 * kk + 1][2], S[2 * kk + 1][3], ah[3], al[3]);
            #pragma unroll
            for (int nt = 0; nt < 8; nt++) {
                uint32_t bh0 = *(const uint32_t*)&sVh[nt * 8 + g][kk * 16 + 2 * tg];
                uint32_t bh1 = *(const uint32_t*)&sVh[nt * 8 + g][kk * 16 + 8 + 2 * tg];
                uint32_t bl0 = *(const uint32_t*)&sVl[nt * 8 + g][kk * 16 + 2 * tg];
                uint32_t bl1 = *(const uint32_t*)&sVl[nt * 8 + g][kk * 16 + 8 + 2 * tg];
                mma_bf16(O[nt][0], O[nt][1], O[nt][2], O[nt][3],
                         ah[0], ah[1], ah[2], ah[3], bh0, bh1);
                mma_bf16(O[nt][0], O[nt][1], O[nt][2], O[nt][3],
                         ah[0], ah[1], ah[2], ah[3], bl0, bl1);
                mma_bf16(O[nt][0], O[nt][1], O[nt][2], O[nt][3],
                         al[0], al[1], al[2], al[3], bh0, bh1);
            }
        }
        __syncthreads();
    }

    // ---- epilogue: normalize, zero invalid queries, write SPLIT ctx ----
    const int tok0 = qt * 64 + warp * 16 + g;
    const int tok1 = tok0 + 8;
    const int qv0 = mask[z * NTOK + tok0];
    const int qv1 = mask[z * NTOK + tok1];
    const float inv0 = (qv0 && l0 > 0.f) ? 1.0f / l0 : 0.f;
    const float inv1 = (qv1 && l1 > 0.f) ? 1.0f / l1 : 0.f;

    #pragma unroll
    for (int nt = 0; nt < 8; nt++) {
        int dk = nt * 8 + 2 * tg;
        size_t i0 = ((size_t)(z * NTOK + tok0)) * DMODEL + h * DK + dk;
        size_t i1 = ((size_t)(z * NTOK + tok1)) * DMODEL + h * DK + dk;
        uint32_t hh, ll;
        split2(O[nt][0] * inv0, O[nt][1] * inv0, hh, ll);
        *(uint32_t*)&Ch[i0] = hh; *(uint32_t*)&Cl[i0] = ll;
        split2(O[nt][2] * inv1, O[nt][3] * inv1, hh, ll);
        *(uint32_t*)&Ch[i1] = hh; *(uint32_t*)&Cl[i1] = ll;
    }
}

// ---------------------------------------------------------------------------
// Out-proj GEMM (reads split ctx, writes fp32 out)
// ---------------------------------------------------------------------------
__global__ __launch_bounds__(256) void gemm_bf3_out(
    const __nv_bfloat16* __restrict__ Ah, const __nv_bfloat16* __restrict__ Al,
    const __nv_bfloat16* __restrict__ Bh, const __nv_bfloat16* __restrict__ Bl,
    float* __restrict__ Out)
{
    const int cb = blockIdx.x;
    const int mb = blockIdx.y;
    float O[8][4] = {};
    gemm_bf3_core(Ah + (size_t)mb * 128 * DMODEL, Al + (size_t)mb * 128 * DMODEL,
                  Bh + (size_t)cb * 64 * DMODEL,  Bl + (size_t)cb * 64 * DMODEL, O);

    const int warp = threadIdx.x >> 5, lane = threadIdx.x & 31;
    const int g = lane >> 2, tg = lane & 3;
    const int row0 = mb * 128 + warp * 16 + g, row1 = row0 + 8;

    #pragma unroll
    for (int nt = 0; nt < 8; nt++) {
        int col = cb * 64 + nt * 8 + 2 * tg;
        *(float2*)&Out[(size_t)row0 * DMODEL + col] = make_float2(O[nt][0], O[nt][1]);
        *(float2*)&Out[(size_t)row1 * DMODEL + col] = make_float2(O[nt][2], O[nt][3]);
    }
}

// ---------------------------------------------------------------------------
// Host entry
// ---------------------------------------------------------------------------
extern "C" void kernel_launch(void* const* d_in, const int* in_sizes, int n_in,
                              void* d_out, int out_size)
{
    const float* x     = (const float*)d_in[0];
    const int*   mask  = (const int*)  d_in[1];
    const float* qproj = (const float*)d_in[2];
    const float* kproj = (const float*)d_in[3];
    const float* vproj = (const float*)d_in[4];
    const float* qbias = (const float*)d_in[5];
    const float* kbias = (const float*)d_in[6];
    const float* vbias = (const float*)d_in[7];
    const float* outw  = (const float*)d_in[8];
    float* out = (float*)d_out;

    __nv_bfloat16 *Xh, *Xl, *BQh, *BQl, *BKh, *BKl, *BVh, *BVl, *Wh, *Wl;
    __nv_bfloat16 *Ch, *Cl, *Qh, *Ql, *Kh, *Kl, *Vth, *Vtl;
    cudaGetSymbolAddress((void**)&Xh,  g_Xh);
    cudaGetSymbolAddress((void**)&Xl,  g_Xl);
    cudaGetSymbolAddress((void**)&BQh, g_BQh);
    cudaGetSymbolAddress((void**)&BQl, g_BQl);
    cudaGetSymbolAddress((void**)&BKh, g_BKh);
    cudaGetSymbolAddress((void**)&BKl, g_BKl);
    cudaGetSymbolAddress((void**)&BVh, g_BVh);
    cudaGetSymbolAddress((void**)&BVl, g_BVl);
    cudaGetSymbolAddress((void**)&Wh,  g_Wh);
    cudaGetSymbolAddress((void**)&Wl,  g_Wl);
    cudaGetSymbolAddress((void**)&Ch,  g_Ch);
    cudaGetSymbolAddress((void**)&Cl,  g_Cl);
    cudaGetSymbolAddress((void**)&Qh,  g_Qh);
    cudaGetSymbolAddress((void**)&Ql,  g_Ql);
    cudaGetSymbolAddress((void**)&Kh,  g_Kh);
    cudaGetSymbolAddress((void**)&Kl,  g_Kl);
    cudaGetSymbolAddress((void**)&Vth, g_Vth);
    cudaGetSymbolAddress((void**)&Vtl, g_Vtl);

    static bool attr_set = false;
    if (!attr_set) {
        cudaFuncSetAttribute(attn_mma,
                             cudaFuncAttributeMaxDynamicSharedMemorySize,
                             2 * STAGE_B);
        attr_set = true;
    }

    // input splits
    split_any_kernel<<<2048, 256>>>(x, Xh, Xl, ROWS * DMODEL);
    split_proj_kernel<<<dim3(DMODEL / 64, HEADS), 256>>>(qproj, BQh, BQl);
    split_proj_kernel<<<dim3(DMODEL / 64, HEADS), 256>>>(kproj, BKh, BKl);
    split_proj_kernel<<<dim3(DMODEL / 64, HEADS), 256>>>(vproj, BVh, BVl);
    split_any_kernel<<<1024, 256>>>(outw, Wh, Wl, DMODEL * DMODEL);

    // QKV projections (tensor-core, split epilogues)
    dim3 gq(HEADS, ROWS / 128);
    gemm_bf3_q<<<gq, 256>>>(Xh, Xl, BQh, BQl, qbias, Qh, Ql);
    gemm_bf3_k<<<gq, 256>>>(Xh, Xl, BKh, BKl, kbias, Kh, Kl);
    gemm_bf3_v<<<gq, 256>>>(Xh, Xl, BVh, BVl, vbias, Vth, Vtl);

    // attention (tensor-core, cp.async pipelined)
    attn_mma<<<dim3(NTOK / 64, ZH), 128, 2 * STAGE_B>>>(
        Qh, Ql, Kh, Kl, Vth, Vtl, mask, Ch, Cl);

    // output projection (tensor-core)
    gemm_bf3_out<<<dim3(DMODEL / 64, ROWS / 128), 256>>>(Ch, Cl, Wh, Wl, out);
}

// round 9
// speedup vs baseline: 4.9796x; 1.1594x over previous
#include <cuda_runtime.h>
#include <cuda_bf16.h>
#include <cstdint>

// Problem constants
#define ZB     2
#define NTOK   2048
#define DMODEL 1024
#define HEADS  16
#define DK     64
#define ROWS   (ZB * NTOK)          // 4096
#define SCALE  0.125f               // DK^-0.5
#define ZH     (ZB * HEADS)         // 32

// ---------------------------------------------------------------------------
// Device scratch (no runtime allocation allowed)
// ---------------------------------------------------------------------------
__device__ __nv_bfloat16 g_Xh[ROWS * DMODEL];   // x split
__device__ __nv_bfloat16 g_Xl[ROWS * DMODEL];
__device__ __nv_bfloat16 g_BQh[HEADS * DK * DMODEL];  // proj split, [h][n][k]
__device__ __nv_bfloat16 g_BQl[HEADS * DK * DMODEL];
__device__ __nv_bfloat16 g_BKh[HEADS * DK * DMODEL];
__device__ __nv_bfloat16 g_BKl[HEADS * DK * DMODEL];
__device__ __nv_bfloat16 g_BVh[HEADS * DK * DMODEL];
__device__ __nv_bfloat16 g_BVl[HEADS * DK * DMODEL];
__device__ __nv_bfloat16 g_Wh[DMODEL * DMODEL]; // out_w split ([n][k] = native)
__device__ __nv_bfloat16 g_Wl[DMODEL * DMODEL];
__device__ __nv_bfloat16 g_Ch[ROWS * DMODEL];   // ctx split (attention output)
__device__ __nv_bfloat16 g_Cl[ROWS * DMODEL];

// pre-split QKV (written directly by GEMM epilogues)
__device__ __nv_bfloat16 g_Qh[ZH * NTOK * DK];  // [zh][n][dk], SCALE folded
__device__ __nv_bfloat16 g_Ql[ZH * NTOK * DK];
__device__ __nv_bfloat16 g_Kh[ZH * NTOK * DK];  // [zh][key][dk]
__device__ __nv_bfloat16 g_Kl[ZH * NTOK * DK];
__device__ __nv_bfloat16 g_Vth[ZH * DK * NTOK]; // transposed: [zh][dk][key]
__device__ __nv_bfloat16 g_Vtl[ZH * DK * NTOK];

extern __shared__ unsigned char smem_dyn[];

// ---------------------------------------------------------------------------
// helpers
// ---------------------------------------------------------------------------
__device__ __forceinline__ uint32_t packb(__nv_bfloat16 x, __nv_bfloat16 y) {
    return (uint32_t)__bfloat16_as_ushort(x) |
           ((uint32_t)__bfloat16_as_ushort(y) << 16);
}
__device__ __forceinline__ void split1(float x, __nv_bfloat16& h, __nv_bfloat16& l) {
    h = __float2bfloat16(x);
    l = __float2bfloat16(x - __bfloat162float(h));
}
__device__ __forceinline__ void split2(float x, float y, uint32_t& hi, uint32_t& lo) {
    __nv_bfloat16 xh, xl, yh, yl;
    split1(x, xh, xl);
    split1(y, yh, yl);
    hi = packb(xh, yh);
    lo = packb(xl, yl);
}

__device__ __forceinline__ void mma4(float* C, const uint32_t* a,
                                     uint32_t b0, uint32_t b1)
{
    asm volatile(
        "mma.sync.aligned.m16n8k16.row.col.f32.bf16.bf16.f32 "
        "{%0,%1,%2,%3},{%4,%5,%6,%7},{%8,%9},{%0,%1,%2,%3};\n"
        : "+f"(C[0]), "+f"(C[1]), "+f"(C[2]), "+f"(C[3])
        : "r"(a[0]), "r"(a[1]), "r"(a[2]), "r"(a[3]), "r"(b0), "r"(b1));
}

__device__ __forceinline__ void ldsm4(uint32_t* r, uint32_t addr) {
    asm volatile("ldmatrix.sync.aligned.m8n8.x4.shared.b16 {%0,%1,%2,%3}, [%4];"
                 : "=r"(r[0]), "=r"(r[1]), "=r"(r[2]), "=r"(r[3]) : "r"(addr));
}

__device__ __forceinline__ void cp_async16(uint32_t dst, const void* src) {
    asm volatile("cp.async.cg.shared.global [%0], [%1], 16;" :: "r"(dst), "l"(src));
}
__device__ __forceinline__ void cp_async4(uint32_t dst, const void* src) {
    asm volatile("cp.async.ca.shared.global [%0], [%1], 4;" :: "r"(dst), "l"(src));
}
__device__ __forceinline__ void cp_commit() {
    asm volatile("cp.async.commit_group;");
}
template <int N>
__device__ __forceinline__ void cp_wait() {
    asm volatile("cp.async.wait_group %0;" :: "n"(N));
}

// ---------------------------------------------------------------------------
// Vectorized elementwise split: fp32 -> (hi, lo) bf16, 4 elems/thread/iter
// ---------------------------------------------------------------------------
__global__ void split_any4_kernel(const float4* __restrict__ in,
                                  uint2* __restrict__ hi,
                                  uint2* __restrict__ lo, int n4)
{
    for (int i = blockIdx.x * blockDim.x + threadIdx.x; i < n4;
         i += gridDim.x * blockDim.x) {
        float4 v = in[i];
        uint32_t h0, l0, h1, l1;
        split2(v.x, v.y, h0, l0);
        split2(v.z, v.w, h1, l1);
        hi[i] = make_uint2(h0, h1);
        lo[i] = make_uint2(l0, l1);
    }
}

// ---------------------------------------------------------------------------
// Proj split + transpose for Q,K,V in one launch (blockIdx.z selects).
// proj[h][d][n] (fp32) -> B[h][n][d] hi/lo (bf16). grid=(16, HEADS, 3)
// ---------------------------------------------------------------------------
__global__ __launch_bounds__(256) void split_proj3_kernel(
    const float* __restrict__ pq, const float* __restrict__ pk,
    const float* __restrict__ pv,
    __nv_bfloat16* __restrict__ qh, __nv_bfloat16* __restrict__ ql,
    __nv_bfloat16* __restrict__ kh, __nv_bfloat16* __restrict__ kl,
    __nv_bfloat16* __restrict__ vh, __nv_bfloat16* __restrict__ vl)
{
    const int dt = blockIdx.x;
    const int h  = blockIdx.y;
    const int w  = blockIdx.z;
    const float* proj = (w == 0) ? pq : (w == 1) ? pk : pv;
    __nv_bfloat16* Bh = (w == 0) ? qh : (w == 1) ? kh : vh;
    __nv_bfloat16* Bl = (w == 0) ? ql : (w == 1) ? kl : vl;

    const int tid = threadIdx.x;
    __shared__ float tile[64][65];

    const float* src = proj + ((size_t)h * DMODEL + dt * 64) * DK;
    #pragma unroll
    for (int it = 0; it < 4; it++) {
        int i4 = tid + it * 256;
        int r  = i4 >> 4;
        int c4 = (i4 & 15) * 4;
        float4 v = *(const float4*)(src + (size_t)r * DK + c4);
        tile[r][c4 + 0] = v.x; tile[r][c4 + 1] = v.y;
        tile[r][c4 + 2] = v.z; tile[r][c4 + 3] = v.w;
    }
    __syncthreads();
    #pragma unroll
    for (int it = 0; it < 16; it++) {
        int o = tid + it * 256;
        int n = o >> 6;
        int j = o & 63;
        float x = tile[j][n];
        __nv_bfloat16 hh, ll;
        split1(x, hh, ll);
        size_t idx = ((size_t)h * DK + n) * DMODEL + dt * 64 + j;
        Bh[idx] = hh;
        Bl[idx] = ll;
    }
}

// ---------------------------------------------------------------------------
// bf16x3 MMA GEMM core: 128x64 block tile, K chunks of 32, cp.async 2-stage,
// ldmatrix fragment loads. 256 threads = 8 warps, warp = 16 rows x 64 cols.
// Stage layout (stride 40 elems = 80 B rows, conflict-free for LDSM):
//   sAh 128x40 (10240 B) | sAl 10240 | sBh 64x40 (5120) | sBl 5120  = 30720 B
// ---------------------------------------------------------------------------
#define G_AH      0
#define G_AL      10240
#define G_BH      20480
#define G_BL      25600
#define G_STAGE   30720

__device__ __forceinline__ void gemm_bf3_core(
    const __nv_bfloat16* __restrict__ Ahb, const __nv_bfloat16* __restrict__ Alb,
    const __nv_bfloat16* __restrict__ Bhb, const __nv_bfloat16* __restrict__ Blb,
    float O[8][4])
{
    const int tid  = threadIdx.x;
    const int warp = tid >> 5;
    const int lane = tid & 31;
    const uint32_t sbase = (uint32_t)__cvta_generic_to_shared(smem_dyn);

    // LDSM per-lane offsets
    const int rA = lane & 15, cA = (lane & 16) >> 1;          // A tiles
    const int rB = (lane & 7) | ((lane & 16) >> 1), cB = lane & 8;  // B tiles
    const uint32_t offA = (uint32_t)(((warp * 16 + rA) * 40 + cA) * 2);
    const uint32_t offB = (uint32_t)((rB * 40 + cB) * 2);

    // cp.async coordinates
    const int ar0 = tid >> 2, ac = (tid & 3);                 // A: 2 chunks/thread
    const int ar1 = (tid + 256) >> 2;
    const int br  = tid >> 2;                                  // B: 1 chunk/thread

    auto issue = [&](int kcid, int stage) {
        const uint32_t sb = sbase + stage * G_STAGE;
        const int kc = kcid * 32;
        cp_async16(sb + G_AH + ar0 * 80 + ac * 16, Ahb + (size_t)ar0 * DMODEL + kc + ac * 8);
        cp_async16(sb + G_AL + ar0 * 80 + ac * 16, Alb + (size_t)ar0 * DMODEL + kc + ac * 8);
        cp_async16(sb + G_AH + ar1 * 80 + ac * 16, Ahb + (size_t)ar1 * DMODEL + kc + ac * 8);
        cp_async16(sb + G_AL + ar1 * 80 + ac * 16, Alb + (size_t)ar1 * DMODEL + kc + ac * 8);
        cp_async16(sb + G_BH + br * 80 + ac * 16,  Bhb + (size_t)br * DMODEL + kc + ac * 8);
        cp_async16(sb + G_BL + br * 80 + ac * 16,  Blb + (size_t)br * DMODEL + kc + ac * 8);
    };

    issue(0, 0);
    cp_commit();

    for (int i = 0; i < 32; i++) {
        if (i + 1 < 32) {
            issue(i + 1, (i + 1) & 1);
            cp_commit();
            cp_wait<1>();
        } else {
            cp_wait<0>();
        }
        __syncthreads();

        const uint32_t sb = sbase + (i & 1) * G_STAGE;
        #pragma unroll
        for (int ks = 0; ks < 2; ks++) {
            uint32_t ah[4], al[4];
            ldsm4(ah, sb + G_AH + offA + ks * 32);
            ldsm4(al, sb + G_AL + offA + ks * 32);
            #pragma unroll
            for (int p = 0; p < 4; p++) {
                uint32_t bh[4], bl[4];
                uint32_t kb = sb + offB + p * 1280 + ks * 32;
                ldsm4(bh, kb + G_BH);
                ldsm4(bl, kb + G_BL);
                mma4(O[2 * p],     ah, bh[0], bh[1]);
                mma4(O[2 * p],     ah, bl[0], bl[1]);
                mma4(O[2 * p],     al, bh[0], bh[1]);
                mma4(O[2 * p + 1], ah, bh[2], bh[3]);
                mma4(O[2 * p + 1], ah, bl[2], bl[3]);
                mma4(O[2 * p + 1], al, bh[2], bh[3]);
            }
        }
        __syncthreads();
    }
}

// Q projection: writes pre-split, pre-scaled Qh/Ql [zh][n][dk]
__global__ __launch_bounds__(256) void gemm_bf3_q(
    const __nv_bfloat16* __restrict__ Ah, const __nv_bfloat16* __restrict__ Al,
    const __nv_bfloat16* __restrict__ Bh, const __nv_bfloat16* __restrict__ Bl,
    const float* __restrict__ bias,
    __nv_bfloat16* __restrict__ Qh, __nv_bfloat16* __restrict__ Ql)
{
    const int h  = blockIdx.x;
    const int mb = blockIdx.y;
    float O[8][4] = {};
    gemm_bf3_core(Ah + (size_t)mb * 128 * DMODEL, Al + (size_t)mb * 128 * DMODEL,
                  Bh + (size_t)h * DK * DMODEL,   Bl + (size_t)h * DK * DMODEL, O);

    const int warp = threadIdx.x >> 5, lane = threadIdx.x & 31;
    const int g = lane >> 2, tg = lane & 3;
    const int row0 = mb * 128 + warp * 16 + g, row1 = row0 + 8;
    const int z = row0 >> 11, n0 = row0 & (NTOK - 1), n1 = row1 & (NTOK - 1);
    const int zh = z * HEADS + h;

    #pragma unroll
    for (int nt = 0; nt < 8; nt++) {
        int col = nt * 8 + 2 * tg;
        float b0 = bias[h * DK + col], b1 = bias[h * DK + col + 1];
        uint32_t hh, ll;
        size_t i0 = ((size_t)zh * NTOK + n0) * DK + col;
        size_t i1 = ((size_t)zh * NTOK + n1) * DK + col;
        split2((O[nt][0] + b0) * SCALE, (O[nt][1] + b1) * SCALE, hh, ll);
        *(uint32_t*)&Qh[i0] = hh; *(uint32_t*)&Ql[i0] = ll;
        split2((O[nt][2] + b0) * SCALE, (O[nt][3] + b1) * SCALE, hh, ll);
        *(uint32_t*)&Qh[i1] = hh; *(uint32_t*)&Ql[i1] = ll;
    }
}

// K projection: writes pre-split Kh/Kl [zh][key][dk]
__global__ __launch_bounds__(256) void gemm_bf3_k(
    const __nv_bfloat16* __restrict__ Ah, const __nv_bfloat16* __restrict__ Al,
    const __nv_bfloat16* __restrict__ Bh, const __nv_bfloat16* __restrict__ Bl,
    const float* __restrict__ bias,
    __nv_bfloat16* __restrict__ Kh, __nv_bfloat16* __restrict__ Kl)
{
    const int h  = blockIdx.x;
    const int mb = blockIdx.y;
    float O[8][4] = {};
    gemm_bf3_core(Ah + (size_t)mb * 128 * DMODEL, Al + (size_t)mb * 128 * DMODEL,
                  Bh + (size_t)h * DK * DMODEL,   Bl + (size_t)h * DK * DMODEL, O);

    const int warp = threadIdx.x >> 5, lane = threadIdx.x & 31;
    const int g = lane >> 2, tg = lane & 3;
    const int row0 = mb * 128 + warp * 16 + g, row1 = row0 + 8;
    const int z = row0 >> 11, n0 = row0 & (NTOK - 1), n1 = row1 & (NTOK - 1);
    const int zh = z * HEADS + h;

    #pragma unroll
    for (int nt = 0; nt < 8; nt++) {
        int col = nt * 8 + 2 * tg;
        float b0 = bias[h * DK + col], b1 = bias[h * DK + col + 1];
        uint32_t hh, ll;
        size_t i0 = ((size_t)zh * NTOK + n0) * DK + col;
        size_t i1 = ((size_t)zh * NTOK + n1) * DK + col;
        split2(O[nt][0] + b0, O[nt][1] + b1, hh, ll);
        *(uint32_t*)&Kh[i0] = hh; *(uint32_t*)&Kl[i0] = ll;
        split2(O[nt][2] + b0, O[nt][3] + b1, hh, ll);
        *(uint32_t*)&Kh[i1] = hh; *(uint32_t*)&Kl[i1] = ll;
    }
}

// V projection: writes pre-split TRANSPOSED Vth/Vtl [zh][dk][key]
__global__ __launch_bounds__(256) void gemm_bf3_v(
    const __nv_bfloat16* __restrict__ Ah, const __nv_bfloat16* __restrict__ Al,
    const __nv_bfloat16* __restrict__ Bh, const __nv_bfloat16* __restrict__ Bl,
    const float* __restrict__ bias,
    __nv_bfloat16* __restrict__ Vth, __nv_bfloat16* __restrict__ Vtl)
{
    const int h  = blockIdx.x;
    const int mb = blockIdx.y;
    float O[8][4] = {};
    gemm_bf3_core(Ah + (size_t)mb * 128 * DMODEL, Al + (size_t)mb * 128 * DMODEL,
                  Bh + (size_t)h * DK * DMODEL,   Bl + (size_t)h * DK * DMODEL, O);

    const int warp = threadIdx.x >> 5, lane = threadIdx.x & 31;
    const int g = lane >> 2, tg = lane & 3;
    const int row0 = mb * 128 + warp * 16 + g, row1 = row0 + 8;
    const int z = row0 >> 11, n0 = row0 & (NTOK - 1), n1 = row1 & (NTOK - 1);
    const size_t baseT = (size_t)(z * HEADS + h) * DK * NTOK;

    #pragma unroll
    for (int nt = 0; nt < 8; nt++) {
        int col = nt * 8 + 2 * tg;
        float b0 = bias[h * DK + col], b1 = bias[h * DK + col + 1];
        #pragma unroll
        for (int j = 0; j < 2; j++) {
            float v0 = O[nt][j]     + (j ? b1 : b0);
            float v1 = O[nt][2 + j] + (j ? b1 : b0);
            __nv_bfloat16 hh, ll;
            split1(v0, hh, ll);
            Vth[baseT + (size_t)(col + j) * NTOK + n0] = hh;
            Vtl[baseT + (size_t)(col + j) * NTOK + n0] = ll;
            split1(v1, hh, ll);
            Vth[baseT + (size_t)(col + j) * NTOK + n1] = hh;
            Vtl[baseT + (size_t)(col + j) * NTOK + n1] = ll;
        }
    }
}

// ---------------------------------------------------------------------------
// Flash attention: bf16x3 MMA + cp.async 2-stage pipeline + ldmatrix frags.
// Block = 128 threads (4 warps), 64 queries/block. grid = (NTOK/64, ZH)
// ---------------------------------------------------------------------------
#define TILE_B      9216        // 64 * 72 * 2
#define STAGE_B     37120       // 4*TILE_B + 256
#define OFF_KH      0
#define OFF_KL      (TILE_B)
#define OFF_VH      (2 * TILE_B)
#define OFF_VL      (3 * TILE_B)
#define OFF_MK      (4 * TILE_B)

__global__ __launch_bounds__(128) void attn_mma(
    const __nv_bfloat16* __restrict__ Qh_g, const __nv_bfloat16* __restrict__ Ql_g,
    const __nv_bfloat16* __restrict__ Kh_g, const __nv_bfloat16* __restrict__ Kl_g,
    const __nv_bfloat16* __restrict__ Vth_g, const __nv_bfloat16* __restrict__ Vtl_g,
    const int* __restrict__ mask,
    __nv_bfloat16* __restrict__ Ch, __nv_bfloat16* __restrict__ Cl)
{
    const int qt   = blockIdx.x;
    const int zh   = blockIdx.y;
    const int z    = zh >> 4;
    const int h    = zh & 15;
    const int tid  = threadIdx.x;
    const int warp = tid >> 5;
    const int lane = tid & 31;
    const int g    = lane >> 2;
    const int tg   = lane & 3;

    typedef __nv_bfloat16(*tile_t)[72];
    const size_t base  = (size_t)zh * NTOK * DK;
    const size_t baseT = (size_t)zh * DK * NTOK;
    const uint32_t smem_u32 = (uint32_t)__cvta_generic_to_shared(smem_dyn);

    // LDSM per-lane offsets (stride 72 elems = 144 B)
    const int rA = lane & 15, cA = (lane & 16) >> 1;
    const int rB = (lane & 7) | ((lane & 16) >> 1), cB = lane & 8;
    const uint32_t offQ = (uint32_t)(((warp * 16 + rA) * 72 + cA) * 2);
    const uint32_t offF = (uint32_t)((rB * 72 + cB) * 2);

    // per-thread tile-load coordinates (4 uint4 rows per array)
    const int lrow[4] = { tid >> 3, (tid + 128) >> 3, (tid + 256) >> 3, (tid + 384) >> 3 };
    const int lc8 = (tid & 7) * 8;

    // ---- stage Q hi/lo tiles into stage-0 smem, extract frags via LDSM ----
    {
        tile_t sQh = (tile_t)(smem_dyn + OFF_KH);
        tile_t sQl = (tile_t)(smem_dyn + OFF_KL);
        const __nv_bfloat16* gq_h = Qh_g + base + (size_t)qt * 64 * DK;
        const __nv_bfloat16* gq_l = Ql_g + base + (size_t)qt * 64 * DK;
        #pragma unroll
        for (int it = 0; it < 4; it++) {
            int row = lrow[it];
            *(uint4*)&sQh[row][lc8] = *(const uint4*)(gq_h + (size_t)row * DK + lc8);
            *(uint4*)&sQl[row][lc8] = *(const uint4*)(gq_l + (size_t)row * DK + lc8);
        }
    }
    __syncthreads();

    uint32_t Qh[4][4], Ql[4][4];
    #pragma unroll
    for (int kk = 0; kk < 4; kk++) {
        ldsm4(Qh[kk], smem_u32 + OFF_KH + offQ + kk * 32);
        ldsm4(Ql[kk], smem_u32 + OFF_KL + offQ + kk * 32);
    }
    __syncthreads();

    // ---- tile issuer (cp.async) ----
    auto issue_tile = [&](int kt, int stage) {
        const uint32_t sb = smem_u32 + stage * STAGE_B;
        const __nv_bfloat16* gkh = Kh_g + base + (size_t)kt * 64 * DK;
        const __nv_bfloat16* gkl = Kl_g + base + (size_t)kt * 64 * DK;
        const __nv_bfloat16* gvh = Vth_g + baseT + kt * 64;
        const __nv_bfloat16* gvl = Vtl_g + baseT + kt * 64;
        #pragma unroll
        for (int it = 0; it < 4; it++) {
            int row = lrow[it];
            uint32_t rowoff = row * 144 + lc8 * 2;
            cp_async16(sb + OFF_KH + rowoff, gkh + (size_t)row * DK + lc8);
            cp_async16(sb + OFF_KL + rowoff, gkl + (size_t)row * DK + lc8);
            cp_async16(sb + OFF_VH + rowoff, gvh + (size_t)row * NTOK + lc8);
            cp_async16(sb + OFF_VL + rowoff, gvl + (size_t)row * NTOK + lc8);
        }
        if (tid < 64)
            cp_async4(sb + OFF_MK + tid * 4, mask + z * NTOK + kt * 64 + tid);
    };

    float O[8][4];
    #pragma unroll
    for (int nt = 0; nt < 8; nt++)
        O[nt][0] = O[nt][1] = O[nt][2] = O[nt][3] = 0.f;
    float m0 = -1e30f, m1 = -1e30f, l0 = 0.f, l1 = 0.f;

    issue_tile(0, 0);
    cp_commit();

    for (int kt = 0; kt < NTOK / 64; kt++) {
        const int cur = kt & 1;
        if (kt + 1 < NTOK / 64) {
            issue_tile(kt + 1, cur ^ 1);
            cp_commit();
            cp_wait<1>();
        } else {
            cp_wait<0>();
        }
        __syncthreads();

        const uint32_t sb = smem_u32 + cur * STAGE_B;
        int* smk = (int*)(smem_dyn + cur * STAGE_B + OFF_MK);

        // ---- S = Q x K^T (bf16x3, LDSM B frags) ----
        float S[8][4];
        #pragma unroll
        for (int p = 0; p < 4; p++) {
            S[2*p][0] = S[2*p][1] = S[2*p][2] = S[2*p][3] = 0.f;
            S[2*p+1][0] = S[2*p+1][1] = S[2*p+1][2] = S[2*p+1][3] = 0.f;
            #pragma unroll
            for (int kk = 0; kk < 4; kk++) {
                uint32_t bh[4], bl[4];
                uint32_t kbb = sb + offF + p * 2304 + kk * 32;
                ldsm4(bh, kbb + OFF_KH);
                ldsm4(bl, kbb + OFF_KL);
                mma4(S[2*p],     Qh[kk], bh[0], bh[1]);
                mma4(S[2*p],     Qh[kk], bl[0], bl[1]);
                mma4(S[2*p],     Ql[kk], bh[0], bh[1]);
                mma4(S[2*p+1],   Qh[kk], bh[2], bh[3]);
                mma4(S[2*p+1],   Qh[kk], bl[2], bl[3]);
                mma4(S[2*p+1],   Ql[kk], bh[2], bh[3]);
            }
        }

        // ---- mask + online softmax ----
        float mx0 = -1e30f, mx1 = -1e30f;
        #pragma unroll
        for (int nt = 0; nt < 8; nt++) {
            #pragma unroll
            for (int j = 0; j < 2; j++) {
                int key = nt * 8 + 2 * tg + j;
                bool ok = smk[key] != 0;
                float v0 = ok ? S[nt][j]     : -1e9f;
                float v1 = ok ? S[nt][2 + j] : -1e9f;
                S[nt][j] = v0; S[nt][2 + j] = v1;
                mx0 = fmaxf(mx0, v0); mx1 = fmaxf(mx1, v1);
            }
        }
        mx0 = fmaxf(mx0, __shfl_xor_sync(0xffffffffu, mx0, 1));
        mx0 = fmaxf(mx0, __shfl_xor_sync(0xffffffffu, mx0, 2));
        mx1 = fmaxf(mx1, __shfl_xor_sync(0xffffffffu, mx1, 1));
        mx1 = fmaxf(mx1, __shfl_xor_sync(0xffffffffu, mx1, 2));

        float mn0 = fmaxf(m0, mx0), mn1 = fmaxf(m1, mx1);
        float corr0 = __expf(m0 - mn0), corr1 = __expf(m1 - mn1);
        m0 = mn0; m1 = mn1;

        float ls0 = 0.f, ls1 = 0.f;
        #pragma unroll
        for (int nt = 0; nt < 8; nt++) {
            S[nt][0] = __expf(S[nt][0] - m0); ls0 += S[nt][0];
            S[nt][1] = __expf(S[nt][1] - m0); ls0 += S[nt][1];
            S[nt][2] = __expf(S[nt][2] - m1); ls1 += S[nt][2];
            S[nt][3] = __expf(S[nt][3] - m1); ls1 += S[nt][3];
        }
        ls0 += __shfl_xor_sync(0xffffffffu, ls0, 1);
        ls0 += __shfl_xor_sync(0xffffffffu, ls0, 2);
        ls1 += __shfl_xor_sync(0xffffffffu, ls1, 1);
        ls1 += __shfl_xor_sync(0xffffffffu, ls1, 2);
        l0 = l0 * corr0 + ls0;
        l1 = l1 * corr1 + ls1;

        #pragma unroll
        for (int nt = 0; nt < 8; nt++) {
            O[nt][0] *= corr0; O[nt][1] *= corr0;
            O[nt][2] *= corr1; O[nt][3] *= corr1;
        }

        // ---- O += P x V (bf16x3, LDSM B frags) ----
        #pragma unroll
        for (int kk = 0; kk < 4; kk++) {
            uint32_t ah[4], al[4];
            split2(S[2 * kk][0],     S[2 * kk][1],     ah[0], al[0]);
            split2(S[2 * kk][2],     S[2 * kk][3],     ah[1], al[1]);
            split2(S[2 * kk + 1][0], S[2 * kk + 1][1], ah[2], al[2]);
            split2(S[2 * kk + 1][2], S[2 * kk + 1][3], ah[3], al[3]);
            #pragma unroll
            for (int p = 0; p < 4; p++) {
                uint32_t bh[4], bl[4];
                uint32_t vbb = sb + offF + p * 2304 + kk * 32;
                ldsm4(bh, vbb + OFF_VH);
                ldsm4(bl, vbb + OFF_VL);
                mma4(O[2*p],     ah, bh[0], bh[1]);
                mma4(O[2*p],     ah, bl[0], bl[1]);
                mma4(O[2*p],     al, bh[0], bh[1]);
                mma4(O[2*p+1],   ah, bh[2], bh[3]);
                mma4(O[2*p+1],   ah, bl[2], bl[3]);
                mma4(O[2*p+1],   al, bh[2], bh[3]);
            }
        }
        __syncthreads();
    }

    // ---- epilogue: normalize, zero invalid queries, write SPLIT ctx ----
    const int tok0 = qt * 64 + warp * 16 + g;
    const int tok1 = tok0 + 8;
    const int qv0 = mask[z * NTOK + tok0];
    const int qv1 = mask[z * NTOK + tok1];
    const float inv0 = (qv0 && l0 > 0.f) ? 1.0f / l0 : 0.f;
    const float inv1 = (qv1 && l1 > 0.f) ? 1.0f / l1 : 0.f;

    #pragma unroll
    for (int nt = 0; nt < 8; nt++) {
        int dk = nt * 8 + 2 * tg;
        size_t i0 = ((size_t)(z * NTOK + tok0)) * DMODEL + h * DK + dk;
        size_t i1 = ((size_t)(z * NTOK + tok1)) * DMODEL + h * DK + dk;
        uint32_t hh, ll;
        split2(O[nt][0] * inv0, O[nt][1] * inv0, hh, ll);
        *(uint32_t*)&Ch[i0] = hh; *(uint32_t*)&Cl[i0] = ll;
        split2(O[nt][2] * inv1, O[nt][3] * inv1, hh, ll);
        *(uint32_t*)&Ch[i1] = hh; *(uint32_t*)&Cl[i1] = ll;
    }
}

// ---------------------------------------------------------------------------
// Out-proj GEMM (reads split ctx, writes fp32 out)
// ---------------------------------------------------------------------------
__global__ __launch_bounds__(256) void gemm_bf3_out(
    const __nv_bfloat16* __restrict__ Ah, const __nv_bfloat16* __restrict__ Al,
    const __nv_bfloat16* __restrict__ Bh, const __nv_bfloat16* __restrict__ Bl,
    float* __restrict__ Out)
{
    const int cb = blockIdx.x;
    const int mb = blockIdx.y;
    float O[8][4] = {};
    gemm_bf3_core(Ah + (size_t)mb * 128 * DMODEL, Al + (size_t)mb * 128 * DMODEL,
                  Bh + (size_t)cb * 64 * DMODEL,  Bl + (size_t)cb * 64 * DMODEL, O);

    const int warp = threadIdx.x >> 5, lane = threadIdx.x & 31;
    const int g = lane >> 2, tg = lane & 3;
    const int row0 = mb * 128 + warp * 16 + g, row1 = row0 + 8;

    #pragma unroll
    for (int nt = 0; nt < 8; nt++) {
        int col = cb * 64 + nt * 8 + 2 * tg;
        *(float2*)&Out[(size_t)row0 * DMODEL + col] = make_float2(O[nt][0], O[nt][1]);
        *(float2*)&Out[(size_t)row1 * DMODEL + col] = make_float2(O[nt][2], O[nt][3]);
    }
}

// ---------------------------------------------------------------------------
// Host entry
// ---------------------------------------------------------------------------
extern "C" void kernel_launch(void* const* d_in, const int* in_sizes, int n_in,
                              void* d_out, int out_size)
{
    const float* x     = (const float*)d_in[0];
    const int*   mask  = (const int*)  d_in[1];
    const float* qproj = (const float*)d_in[2];
    const float* kproj = (const float*)d_in[3];
    const float* vproj = (const float*)d_in[4];
    const float* qbias = (const float*)d_in[5];
    const float* kbias = (const float*)d_in[6];
    const float* vbias = (const float*)d_in[7];
    const float* outw  = (const float*)d_in[8];
    float* out = (float*)d_out;

    __nv_bfloat16 *Xh, *Xl, *BQh, *BQl, *BKh, *BKl, *BVh, *BVl, *Wh, *Wl;
    __nv_bfloat16 *Ch, *Cl, *Qh, *Ql, *Kh, *Kl, *Vth, *Vtl;
    cudaGetSymbolAddress((void**)&Xh,  g_Xh);
    cudaGetSymbolAddress((void**)&Xl,  g_Xl);
    cudaGetSymbolAddress((void**)&BQh, g_BQh);
    cudaGetSymbolAddress((void**)&BQl, g_BQl);
    cudaGetSymbolAddress((void**)&BKh, g_BKh);
    cudaGetSymbolAddress((void**)&BKl, g_BKl);
    cudaGetSymbolAddress((void**)&BVh, g_BVh);
    cudaGetSymbolAddress((void**)&BVl, g_BVl);
    cudaGetSymbolAddress((void**)&Wh,  g_Wh);
    cudaGetSymbolAddress((void**)&Wl,  g_Wl);
    cudaGetSymbolAddress((void**)&Ch,  g_Ch);
    cudaGetSymbolAddress((void**)&Cl,  g_Cl);
    cudaGetSymbolAddress((void**)&Qh,  g_Qh);
    cudaGetSymbolAddress((void**)&Ql,  g_Ql);
    cudaGetSymbolAddress((void**)&Kh,  g_Kh);
    cudaGetSymbolAddress((void**)&Kl,  g_Kl);
    cudaGetSymbolAddress((void**)&Vth, g_Vth);
    cudaGetSymbolAddress((void**)&Vtl, g_Vtl);

    static bool attr_set = false;
    if (!attr_set) {
        cudaFuncSetAttribute(attn_mma,
                             cudaFuncAttributeMaxDynamicSharedMemorySize, 2 * STAGE_B);
        cudaFuncSetAttribute(gemm_bf3_q,
                             cudaFuncAttributeMaxDynamicSharedMemorySize, 2 * G_STAGE);
        cudaFuncSetAttribute(gemm_bf3_k,
                             cudaFuncAttributeMaxDynamicSharedMemorySize, 2 * G_STAGE);
        cudaFuncSetAttribute(gemm_bf3_v,
                             cudaFuncAttributeMaxDynamicSharedMemorySize, 2 * G_STAGE);
        cudaFuncSetAttribute(gemm_bf3_out,
                             cudaFuncAttributeMaxDynamicSharedMemorySize, 2 * G_STAGE);
        attr_set = true;
    }

    // input splits
    split_any4_kernel<<<1024, 256>>>((const float4*)x, (uint2*)Xh, (uint2*)Xl,
                                     ROWS * DMODEL / 4);
    split_proj3_kernel<<<dim3(DMODEL / 64, HEADS, 3), 256>>>(
        qproj, kproj, vproj, BQh, BQl, BKh, BKl, BVh, BVl);
    split_any4_kernel<<<512, 256>>>((const float4*)outw, (uint2*)Wh, (uint2*)Wl,
                                    DMODEL * DMODEL / 4);

    // QKV projections (tensor-core, pipelined, split epilogues)
    dim3 gq(HEADS, ROWS / 128);
    gemm_bf3_q<<<gq, 256, 2 * G_STAGE>>>(Xh, Xl, BQh, BQl, qbias, Qh, Ql);
    gemm_bf3_k<<<gq, 256, 2 * G_STAGE>>>(Xh, Xl, BKh, BKl, kbias, Kh, Kl);
    gemm_bf3_v<<<gq, 256, 2 * G_STAGE>>>(Xh, Xl, BVh, BVl, vbias, Vth, Vtl);

    // attention (tensor-core, cp.async pipelined, LDSM frags)
    attn_mma<<<dim3(NTOK / 64, ZH), 128, 2 * STAGE_B>>>(
        Qh, Ql, Kh, Kl, Vth, Vtl, mask, Ch, Cl);

    // output projection (tensor-core, pipelined)
    gemm_bf3_out<<<dim3(DMODEL / 64, ROWS / 128), 256, 2 * G_STAGE>>>(
        Ch, Cl, Wh, Wl, out);
}